// round 9
// baseline (speedup 1.0000x reference)
#include <cuda_runtime.h>
#include <cuda_fp16.h>
#include <cstdint>
#include <math.h>

#define BB 2
#define SS 2048
#define DIM 1536
#define NH 12
#define HD 128
#define SIGMA 12
#define M_TOT (BB * SS)      // 4096
#define N_QKV (3 * DIM)      // 4608

// ---------------- scratch (__device__ globals; allocation-free rule) -------
// GEMM A/B operands are fp16 in "chunk-permuted" layout: within each 32-col
// group, chunk t (8 halves) = cols {2t,2t+1,8+2t,9+2t,16+2t,17+2t,24+2t,25+2t}.
__device__ __half g_xh[(size_t)M_TOT * DIM];       // permuted x
__device__ __half g_wqkvT[(size_t)N_QKV * DIM];    // permuted Wqkv^T
__device__ __half g_woutT[(size_t)DIM * DIM];      // permuted Wout^T
__device__ __half g_qkvh[(size_t)M_TOT * N_QKV];   // QKV output (fp16, standard)
__device__ __half g_att[(size_t)M_TOT * DIM];      // attention out (permuted)

// ---------------- helpers ---------------------------------------------------
__device__ __forceinline__ uint32_t smem_u32(const void* p) {
    uint32_t a;
    asm("{ .reg .u64 t; cvta.to.shared.u64 t, %1; cvt.u32.u64 %0, t; }"
        : "=r"(a) : "l"(p));
    return a;
}
__device__ __forceinline__ void cp16(uint32_t dst, const void* src) {
    asm volatile("cp.async.cg.shared.global [%0], [%1], 16;"
                 :: "r"(dst), "l"(src) : "memory");
}
__device__ __forceinline__ void cp_commit() {
    asm volatile("cp.async.commit_group;" ::: "memory");
}
template <int N>
__device__ __forceinline__ void cp_wait() {
    asm volatile("cp.async.wait_group %0;" :: "n"(N) : "memory");
}
// NOTE: non-volatile — results are consumed by the epilogue, and the compiler
// is free to schedule/interleave these with fragment loads.
__device__ __forceinline__ void mma_f16(float* c,
                                        uint32_t a0, uint32_t a1, uint32_t a2, uint32_t a3,
                                        uint32_t b0, uint32_t b1) {
    asm("mma.sync.aligned.m16n8k16.row.col.f32.f16.f16.f32 "
        "{%0,%1,%2,%3}, {%4,%5,%6,%7}, {%8,%9}, {%0,%1,%2,%3};"
        : "+f"(c[0]), "+f"(c[1]), "+f"(c[2]), "+f"(c[3])
        : "r"(a0), "r"(a1), "r"(a2), "r"(a3), "r"(b0), "r"(b1));
}
#define F4U(v, i) (reinterpret_cast<const uint32_t*>(&(v))[i])

// ---------------- fp16 GEMM: CTA BN(128) x BMT, 4 warps of (BMT/2)x64 -------
// A:[M,K] permuted halves, BT:[N,K] permuted halves, C standard (OutT).
#define BN 128
#define BKH 64               // halves per k-iter (128B rows)
#define STAGES 3

template <int BMT, typename OutT>
__global__ __launch_bounds__(128, 2)
void gemm_f16_mma(const __half* __restrict__ A, const __half* __restrict__ BT,
                  const float* __restrict__ bias, OutT* __restrict__ C,
                  int Ndim, int K) {
    constexpr int MT = BMT / 32;          // m16 tiles per warp
    constexpr int A_ST = BMT * 128;       // bytes per A stage
    constexpr int B_ST = BN * 128;
    constexpr int STG = A_ST + B_ST;
    extern __shared__ char smem[];
    const uint32_t sbase = smem_u32(smem);

    const int tid = threadIdx.x;
    const int wid = tid >> 5;
    const int lane = tid & 31;
    const int g = lane >> 2;              // 0..7
    const int t = lane & 3;               // 0..3
    const int warp_m = wid >> 1;          // 0..1
    const int warp_n = wid & 1;           // 0..1
    const int m0 = blockIdx.y * BMT;
    const int n0 = blockIdx.x * BN;
    const int KT = K / BKH;

    const int lc = tid & 7;               // loader chunk
    const int lr = tid >> 3;              // loader row base (0..15)

    auto load_stage = [&](int stage, int kt) {
        const __half* Ak = A + (size_t)m0 * K + kt * BKH;
        const __half* Bk = BT + (size_t)n0 * K + kt * BKH;
        const uint32_t sA = sbase + stage * STG;
        const uint32_t sB = sA + A_ST;
#pragma unroll
        for (int i = 0; i < BMT / 16; i++) {
            int row = i * 16 + lr;
            cp16(sA + row * 128 + (((lc + ((row & 1) << 2)) & 7) << 4),
                 Ak + (size_t)row * K + lc * 8);
        }
#pragma unroll
        for (int i = 0; i < BN / 16; i++) {
            int row = i * 16 + lr;
            cp16(sB + row * 128 + (((lc + ((row & 1) << 2)) & 7) << 4),
                 Bk + (size_t)row * K + lc * 8);
        }
        cp_commit();
    };

    float acc[MT][8][4];
#pragma unroll
    for (int i = 0; i < MT; i++)
#pragma unroll
        for (int j = 0; j < 8; j++)
#pragma unroll
            for (int r = 0; r < 4; r++) acc[i][j][r] = 0.0f;

    load_stage(0, 0);
    load_stage(1, 1);

    const int gp = g & 1;                 // row parity for all fragment rows

    for (int kt = 0; kt < KT; ++kt) {
        cp_wait<1>();
        __syncthreads();
        if (kt + 2 < KT) load_stage((kt + 2) % STAGES, kt + 2);

        const char* sA = smem + (kt % STAGES) * STG;
        const char* sB = sA + A_ST;

#pragma unroll
        for (int h = 0; h < 2; h++) {
            const int ch = t + ((h ^ gp) << 2);   // swizzled chunk, 0..7
            float4 av[MT][2];
#pragma unroll
            for (int mt = 0; mt < MT; mt++)
#pragma unroll
                for (int rr = 0; rr < 2; rr++) {
                    int row = warp_m * (BMT / 2) + mt * 16 + rr * 8 + g;
                    av[mt][rr] = *(const float4*)(sA + row * 128 + ch * 16);
                }
            float4 bv[8];
#pragma unroll
            for (int nt = 0; nt < 8; nt++) {
                int row = warp_n * 64 + nt * 8 + g;
                bv[nt] = *(const float4*)(sB + row * 128 + ch * 16);
            }
            // step-major order: all step-0 HMMAs (independent), then all
            // step-1s. Dependency distance per accumulator = MT*8 ops.
#pragma unroll
            for (int mt = 0; mt < MT; mt++)
#pragma unroll
                for (int nt = 0; nt < 8; nt++)
                    mma_f16(acc[mt][nt],
                            F4U(av[mt][0], 0), F4U(av[mt][1], 0),
                            F4U(av[mt][0], 1), F4U(av[mt][1], 1),
                            F4U(bv[nt], 0), F4U(bv[nt], 1));
#pragma unroll
            for (int mt = 0; mt < MT; mt++)
#pragma unroll
                for (int nt = 0; nt < 8; nt++)
                    mma_f16(acc[mt][nt],
                            F4U(av[mt][0], 2), F4U(av[mt][1], 2),
                            F4U(av[mt][0], 3), F4U(av[mt][1], 3),
                            F4U(bv[nt], 2), F4U(bv[nt], 3));
        }
    }

    // epilogue: bias in fp32, output fp32 or fp16
#pragma unroll
    for (int mt = 0; mt < MT; mt++) {
        const int r0 = m0 + warp_m * (BMT / 2) + mt * 16 + g;
#pragma unroll
        for (int nt = 0; nt < 8; nt++) {
            const int col = n0 + warp_n * 64 + nt * 8 + 2 * t;
            const float2 bv = *reinterpret_cast<const float2*>(bias + col);
            float2 o0, o1;
            o0.x = acc[mt][nt][0] + bv.x;
            o0.y = acc[mt][nt][1] + bv.y;
            o1.x = acc[mt][nt][2] + bv.x;
            o1.y = acc[mt][nt][3] + bv.y;
            if constexpr (sizeof(OutT) == 4) {
                float* Cf = (float*)C;
                *reinterpret_cast<float2*>(Cf + (size_t)r0 * Ndim + col) = o0;
                *reinterpret_cast<float2*>(Cf + (size_t)(r0 + 8) * Ndim + col) = o1;
            } else {
                __half* Ch = (__half*)C;
                __half2 h0 = __floats2half2_rn(o0.x, o0.y);
                __half2 h1 = __floats2half2_rn(o1.x, o1.y);
                *reinterpret_cast<__half2*>(Ch + (size_t)r0 * Ndim + col) = h0;
                *reinterpret_cast<__half2*>(Ch + (size_t)(r0 + 8) * Ndim + col) = h1;
            }
        }
    }
}

// ---------------- pre-pass kernels (write permuted fp16 layouts) ------------
__global__ __launch_bounds__(256)
void x_to_half_perm(const float* __restrict__ in, __half* __restrict__ out) {
    int q = blockIdx.x * blockDim.x + threadIdx.x;
    if (q >= M_TOT * DIM / 8) return;
    int r = q / (DIM / 8);
    int c = q % (DIM / 8);
    int grp = c >> 2, t = c & 3;
    const float* src = in + (size_t)r * DIM + grp * 32 + 2 * t;
    __half2 h0 = __floats2half2_rn(src[0], src[1]);
    __half2 h1 = __floats2half2_rn(src[8], src[9]);
    __half2 h2 = __floats2half2_rn(src[16], src[17]);
    __half2 h3 = __floats2half2_rn(src[24], src[25]);
    uint4 o;
    o.x = *reinterpret_cast<uint32_t*>(&h0);
    o.y = *reinterpret_cast<uint32_t*>(&h1);
    o.z = *reinterpret_cast<uint32_t*>(&h2);
    o.w = *reinterpret_cast<uint32_t*>(&h3);
    reinterpret_cast<uint4*>(out)[q] = o;
}

// in: R x C row-major fp32; out: C x R halves, chunk-permuted along R(=K)
__global__ __launch_bounds__(1024)
void transpose_half_perm(const float* __restrict__ in, __half* __restrict__ out,
                         int R, int C) {
    __shared__ float tbuf[32][33];
    int c = blockIdx.x * 32 + threadIdx.x;
    int r = blockIdx.y * 32 + threadIdx.y;
    tbuf[threadIdx.y][threadIdx.x] = in[(size_t)r * C + c];
    __syncthreads();
    int oc = blockIdx.y * 32 + threadIdx.x;     // K index
    int orow = blockIdx.x * 32 + threadIdx.y;   // N index
    int w = oc & 31;
    int ppos = (oc & ~31) | (((w >> 1) & 3) << 3) | ((w >> 3) << 1) | (w & 1);
    out[(size_t)orow * R + ppos] = __float2half_rn(tbuf[threadIdx.x][threadIdx.y]);
}

// ---------------- anchor attention (one warp per (b,h,s), fp16 QKV) ---------
__global__ __launch_bounds__(256)
void anchor_attn_kernel(const float* __restrict__ gs) {
    const int gw = (blockIdx.x * blockDim.x + threadIdx.x) >> 5;
    const int lane = threadIdx.x & 31;

    const int s = gw % SS;
    const int h = (gw / SS) % NH;
    const int b = gw / (SS * NH);

    const float g0 = gs[0], g1 = gs[1], g2 = gs[2];
    const float mx = fmaxf(g0, fmaxf(g1, g2));
    const float lse = mx + logf(expf(g0 - mx) + expf(g1 - mx) + expf(g2 - mx));
    const float lw0 = g0 - lse, lw1 = g1 - lse, lw2 = g2 - lse;

    const __half* base = g_qkvh + (size_t)b * SS * N_QKV;
    const int hc = h * HD + lane * 4;

    float4 q;
    {
        const __half2* qp = reinterpret_cast<const __half2*>(
            base + (size_t)s * N_QKV + hc);
        float2 a = __half22float2(qp[0]);
        float2 c = __half22float2(qp[1]);
        q = make_float4(a.x, a.y, c.x, c.y);
    }

    int aidx[SIGMA];
    const int offs[10] = {-3, -2, -1, 1, 2, 3, -10, -5, 5, 10};
#pragma unroll
    for (int a = 0; a < 10; a++) {
        int j = s + offs[a];
        aidx[a] = j < 0 ? 0 : (j > SS - 1 ? SS - 1 : j);
    }
    aidx[10] = 0;
    aidx[11] = SS - 1;

    const float scale = 0.08838834764831845f;
    float sc[SIGMA];
#pragma unroll
    for (int a = 0; a < SIGMA; a++) {
        const __half2* kp = reinterpret_cast<const __half2*>(
            base + (size_t)aidx[a] * N_QKV + DIM + hc);
        float2 k0 = __half22float2(kp[0]);
        float2 k1 = __half22float2(kp[1]);
        float d = q.x * k0.x + q.y * k0.y + q.z * k1.x + q.w * k1.y;
#pragma unroll
        for (int o = 16; o > 0; o >>= 1)
            d += __shfl_xor_sync(0xffffffffu, d, o);
        const float lw = (a < 6) ? lw0 : ((a < 10) ? lw1 : lw2);
        sc[a] = d * scale + lw;
    }

    float m = sc[0];
#pragma unroll
    for (int a = 1; a < SIGMA; a++) m = fmaxf(m, sc[a]);
    float sum = 0.0f;
#pragma unroll
    for (int a = 0; a < SIGMA; a++) { sc[a] = __expf(sc[a] - m); sum += sc[a]; }
    const float inv = 1.0f / sum;

    // permuted-chunk dims this lane owns:
    // chunk c = lane>>1 (within head), halfsel = lane&1
    // dims = G*32 + 16*halfsel + 2t + {0,1,8,9}, G = c>>2, t = c&3
    const int cch = lane >> 1;
    const int hs = lane & 1;
    const int d0 = h * HD + (cch >> 2) * 32 + hs * 16 + 2 * (cch & 3);
    float4 acc = make_float4(0.f, 0.f, 0.f, 0.f);
#pragma unroll
    for (int a = 0; a < SIGMA; a++) {
        const float w = sc[a] * inv;
        const __half* vr = base + (size_t)aidx[a] * N_QKV + 2 * DIM + d0;
        float2 v0 = __half22float2(*reinterpret_cast<const __half2*>(vr));
        float2 v1 = __half22float2(*reinterpret_cast<const __half2*>(vr + 8));
        acc.x += w * v0.x; acc.y += w * v0.y;
        acc.z += w * v1.x; acc.w += w * v1.y;
    }

    __half2 p0 = __floats2half2_rn(acc.x, acc.y);
    __half2 p1 = __floats2half2_rn(acc.z, acc.w);
    uint2 o;
    o.x = *reinterpret_cast<uint32_t*>(&p0);
    o.y = *reinterpret_cast<uint32_t*>(&p1);
    *reinterpret_cast<uint2*>(
        g_att + (size_t)(b * SS + s) * DIM + h * HD + cch * 8 + hs * 4) = o;
}

// ---------------------------------------------------------------------------
extern "C" void kernel_launch(void* const* d_in, const int* in_sizes, int n_in,
                              void* d_out, int out_size) {
    const float* x    = (const float*)d_in[0];
    const float* Wqkv = (const float*)d_in[1];
    const float* bqkv = (const float*)d_in[2];
    const float* Wout = (const float*)d_in[3];
    const float* bout = (const float*)d_in[4];
    const float* gsc  = (const float*)d_in[5];
    float* out = (float*)d_out;

    __half *pxh, *pwqkvT, *pwoutT, *patt, *pqkvh;
    cudaGetSymbolAddress((void**)&pxh, g_xh);
    cudaGetSymbolAddress((void**)&pwqkvT, g_wqkvT);
    cudaGetSymbolAddress((void**)&pwoutT, g_woutT);
    cudaGetSymbolAddress((void**)&pqkvh, g_qkvh);
    cudaGetSymbolAddress((void**)&patt, g_att);

    constexpr int SM128 = STAGES * (128 * 128 + BN * 128);  // 98304
    constexpr int SM64  = STAGES * (64 * 128 + BN * 128);   // 73728

    static bool attr_set = false;
    if (!attr_set) {
        cudaFuncSetAttribute((const void*)gemm_f16_mma<128, __half>,
                             cudaFuncAttributeMaxDynamicSharedMemorySize, SM128);
        cudaFuncSetAttribute((const void*)gemm_f16_mma<64, float>,
                             cudaFuncAttributeMaxDynamicSharedMemorySize, SM64);
        attr_set = true;
    }

    // 1) x -> permuted fp16
    x_to_half_perm<<<(M_TOT * DIM / 8 + 255) / 256, 256>>>(x, pxh);
    // 2) transpose + permute weights -> fp16
    transpose_half_perm<<<dim3(N_QKV / 32, DIM / 32), dim3(32, 32)>>>(Wqkv, pwqkvT, DIM, N_QKV);
    transpose_half_perm<<<dim3(DIM / 32, DIM / 32), dim3(32, 32)>>>(Wout, pwoutT, DIM, DIM);

    // 3) QKV projection: (4096x1536) @ (1536x4608) -> fp16
    gemm_f16_mma<128, __half><<<dim3(N_QKV / BN, M_TOT / 128), 128, SM128>>>(
        pxh, pwqkvT, bqkv, pqkvh, N_QKV, DIM);

    // 4) anchor attention
    anchor_attn_kernel<<<BB * NH * SS * 32 / 256, 256>>>(gsc);

    // 5) output projection: (4096x1536) @ (1536x1536) -> fp32 out
    gemm_f16_mma<64, float><<<dim3(DIM / BN, M_TOT / 64), 128, SM64>>>(
        patt, pwoutT, bout, out, DIM, DIM);
}

// round 10
// speedup vs baseline: 1.0329x; 1.0329x over previous
#include <cuda_runtime.h>
#include <cuda_fp16.h>
#include <cstdint>
#include <math.h>

#define BB 2
#define SS 2048
#define DIM 1536
#define NH 12
#define HD 128
#define SIGMA 12
#define M_TOT (BB * SS)      // 4096
#define N_QKV (3 * DIM)      // 4608

// ---------------- scratch (__device__ globals; allocation-free rule) -------
// GEMM A/B operands are fp16 in "chunk-permuted" layout: within each 32-col
// group, chunk t (8 halves) = cols {2t,2t+1,8+2t,9+2t,16+2t,17+2t,24+2t,25+2t}.
__device__ __half g_xh[(size_t)M_TOT * DIM];       // permuted x
__device__ __half g_wqkvT[(size_t)N_QKV * DIM];    // permuted Wqkv^T
__device__ __half g_woutT[(size_t)DIM * DIM];      // permuted Wout^T
__device__ __half g_qkvh[(size_t)M_TOT * N_QKV];   // QKV output (fp16, standard)
__device__ __half g_att[(size_t)M_TOT * DIM];      // attention out (permuted)

// ---------------- helpers ---------------------------------------------------
__device__ __forceinline__ uint32_t smem_u32(const void* p) {
    uint32_t a;
    asm("{ .reg .u64 t; cvta.to.shared.u64 t, %1; cvt.u32.u64 %0, t; }"
        : "=r"(a) : "l"(p));
    return a;
}
__device__ __forceinline__ void cp16(uint32_t dst, const void* src) {
    asm volatile("cp.async.cg.shared.global [%0], [%1], 16;"
                 :: "r"(dst), "l"(src) : "memory");
}
__device__ __forceinline__ void cp_commit() {
    asm volatile("cp.async.commit_group;" ::: "memory");
}
template <int N>
__device__ __forceinline__ void cp_wait() {
    asm volatile("cp.async.wait_group %0;" :: "n"(N) : "memory");
}
__device__ __forceinline__ void mma_f16(float* c,
                                        uint32_t a0, uint32_t a1, uint32_t a2, uint32_t a3,
                                        uint32_t b0, uint32_t b1) {
    asm("mma.sync.aligned.m16n8k16.row.col.f32.f16.f16.f32 "
        "{%0,%1,%2,%3}, {%4,%5,%6,%7}, {%8,%9}, {%0,%1,%2,%3};"
        : "+f"(c[0]), "+f"(c[1]), "+f"(c[2]), "+f"(c[3])
        : "r"(a0), "r"(a1), "r"(a2), "r"(a3), "r"(b0), "r"(b1));
}
#define F4U(v, i) (reinterpret_cast<const uint32_t*>(&(v))[i])

// ---------------- fp16 GEMM: CTA BN(128) x BMT(64), 4 warps of 32x64 --------
// A:[M,K] permuted halves, BT:[N,K] permuted halves, C standard (OutT).
// 3 CTAs/SM target: smem 72KB/CTA, regs <= 170.
#define BN 128
#define BKH 64               // halves per k-iter (128B rows)
#define STAGES 3

template <int BMT, typename OutT>
__global__ __launch_bounds__(128, 3)
void gemm_f16_mma(const __half* __restrict__ A, const __half* __restrict__ BT,
                  const float* __restrict__ bias, OutT* __restrict__ C,
                  int Ndim, int K) {
    constexpr int MT = BMT / 32;          // m16 tiles per warp (2 for BMT=64)
    constexpr int A_ST = BMT * 128;       // bytes per A stage
    constexpr int B_ST = BN * 128;
    constexpr int STG = A_ST + B_ST;
    extern __shared__ char smem[];
    const uint32_t sbase = smem_u32(smem);

    const int tid = threadIdx.x;
    const int wid = tid >> 5;
    const int lane = tid & 31;
    const int g = lane >> 2;              // 0..7
    const int t = lane & 3;               // 0..3
    const int warp_m = wid >> 1;          // 0..1
    const int warp_n = wid & 1;           // 0..1
    const int m0 = blockIdx.y * BMT;
    const int n0 = blockIdx.x * BN;
    const int KT = K / BKH;

    const int lc = tid & 7;               // loader chunk
    const int lr = tid >> 3;              // loader row base (0..15)

    auto load_stage = [&](int stage, int kt) {
        const __half* Ak = A + (size_t)m0 * K + kt * BKH;
        const __half* Bk = BT + (size_t)n0 * K + kt * BKH;
        const uint32_t sA = sbase + stage * STG;
        const uint32_t sB = sA + A_ST;
#pragma unroll
        for (int i = 0; i < BMT / 16; i++) {
            int row = i * 16 + lr;
            cp16(sA + row * 128 + (((lc + ((row & 1) << 2)) & 7) << 4),
                 Ak + (size_t)row * K + lc * 8);
        }
#pragma unroll
        for (int i = 0; i < BN / 16; i++) {
            int row = i * 16 + lr;
            cp16(sB + row * 128 + (((lc + ((row & 1) << 2)) & 7) << 4),
                 Bk + (size_t)row * K + lc * 8);
        }
        cp_commit();
    };

    float acc[MT][8][4];
#pragma unroll
    for (int i = 0; i < MT; i++)
#pragma unroll
        for (int j = 0; j < 8; j++)
#pragma unroll
            for (int r = 0; r < 4; r++) acc[i][j][r] = 0.0f;

    load_stage(0, 0);
    load_stage(1, 1);

    const int gp = g & 1;                 // row parity for all fragment rows

    for (int kt = 0; kt < KT; ++kt) {
        cp_wait<1>();
        __syncthreads();
        if (kt + 2 < KT) load_stage((kt + 2) % STAGES, kt + 2);

        const char* sA = smem + (kt % STAGES) * STG;
        const char* sB = sA + A_ST;

#pragma unroll
        for (int h = 0; h < 2; h++) {
            const int ch = t + ((h ^ gp) << 2);   // swizzled chunk, 0..7
            float4 av[MT][2];
#pragma unroll
            for (int mt = 0; mt < MT; mt++)
#pragma unroll
                for (int rr = 0; rr < 2; rr++) {
                    int row = warp_m * (BMT / 2) + mt * 16 + rr * 8 + g;
                    av[mt][rr] = *(const float4*)(sA + row * 128 + ch * 16);
                }
            float4 bv[8];
#pragma unroll
            for (int nt = 0; nt < 8; nt++) {
                int row = warp_n * 64 + nt * 8 + g;
                bv[nt] = *(const float4*)(sB + row * 128 + ch * 16);
            }
#pragma unroll
            for (int mt = 0; mt < MT; mt++)
#pragma unroll
                for (int nt = 0; nt < 8; nt++)
                    mma_f16(acc[mt][nt],
                            F4U(av[mt][0], 0), F4U(av[mt][1], 0),
                            F4U(av[mt][0], 1), F4U(av[mt][1], 1),
                            F4U(bv[nt], 0), F4U(bv[nt], 1));
#pragma unroll
            for (int mt = 0; mt < MT; mt++)
#pragma unroll
                for (int nt = 0; nt < 8; nt++)
                    mma_f16(acc[mt][nt],
                            F4U(av[mt][0], 2), F4U(av[mt][1], 2),
                            F4U(av[mt][0], 3), F4U(av[mt][1], 3),
                            F4U(bv[nt], 2), F4U(bv[nt], 3));
        }
    }

    // epilogue: bias in fp32, output fp32 or fp16
#pragma unroll
    for (int mt = 0; mt < MT; mt++) {
        const int r0 = m0 + warp_m * (BMT / 2) + mt * 16 + g;
#pragma unroll
        for (int nt = 0; nt < 8; nt++) {
            const int col = n0 + warp_n * 64 + nt * 8 + 2 * t;
            const float2 bv = *reinterpret_cast<const float2*>(bias + col);
            float2 o0, o1;
            o0.x = acc[mt][nt][0] + bv.x;
            o0.y = acc[mt][nt][1] + bv.y;
            o1.x = acc[mt][nt][2] + bv.x;
            o1.y = acc[mt][nt][3] + bv.y;
            if constexpr (sizeof(OutT) == 4) {
                float* Cf = (float*)C;
                *reinterpret_cast<float2*>(Cf + (size_t)r0 * Ndim + col) = o0;
                *reinterpret_cast<float2*>(Cf + (size_t)(r0 + 8) * Ndim + col) = o1;
            } else {
                __half* Ch = (__half*)C;
                __half2 h0 = __floats2half2_rn(o0.x, o0.y);
                __half2 h1 = __floats2half2_rn(o1.x, o1.y);
                *reinterpret_cast<__half2*>(Ch + (size_t)r0 * Ndim + col) = h0;
                *reinterpret_cast<__half2*>(Ch + (size_t)(r0 + 8) * Ndim + col) = h1;
            }
        }
    }
}

// ---------------- fused pre-pass: x perm + both weight transposes -----------
__device__ __forceinline__ void transpose_tile(const float* __restrict__ in,
                                               __half* __restrict__ out,
                                               int R, int C, int bx, int by,
                                               int tid) {
    __shared__ float tbuf[32][33];
    const int tx = tid & 31;
    const int ty = tid >> 5;              // 0..7
#pragma unroll
    for (int i = 0; i < 4; i++) {
        int r = by * 32 + ty + i * 8;
        tbuf[ty + i * 8][tx] = in[(size_t)r * C + bx * 32 + tx];
    }
    __syncthreads();
    const int oc = by * 32 + tx;          // K index
    const int w = oc & 31;
    const int ppos = (oc & ~31) | (((w >> 1) & 3) << 3) | ((w >> 3) << 1) | (w & 1);
#pragma unroll
    for (int i = 0; i < 4; i++) {
        int orow = bx * 32 + ty + i * 8;  // N index
        out[(size_t)orow * R + ppos] = __float2half_rn(tbuf[tx][ty + i * 8]);
    }
}

#define NB_X   (M_TOT * DIM / 8 / 256)          // 3072
#define NB_WQ  ((N_QKV / 32) * (DIM / 32))      // 6912
#define NB_WO  ((DIM / 32) * (DIM / 32))        // 2304

__global__ __launch_bounds__(256)
void prepass_fused(const float* __restrict__ x, const float* __restrict__ Wqkv,
                   const float* __restrict__ Wout,
                   __half* __restrict__ xh, __half* __restrict__ wqkvT,
                   __half* __restrict__ woutT) {
    const int bid = blockIdx.x;
    const int tid = threadIdx.x;
    if (bid < NB_X) {
        int q = bid * 256 + tid;
        int r = q / (DIM / 8);
        int c = q % (DIM / 8);
        int grp = c >> 2, t = c & 3;
        const float* src = x + (size_t)r * DIM + grp * 32 + 2 * t;
        __half2 h0 = __floats2half2_rn(src[0], src[1]);
        __half2 h1 = __floats2half2_rn(src[8], src[9]);
        __half2 h2 = __floats2half2_rn(src[16], src[17]);
        __half2 h3 = __floats2half2_rn(src[24], src[25]);
        uint4 o;
        o.x = *reinterpret_cast<uint32_t*>(&h0);
        o.y = *reinterpret_cast<uint32_t*>(&h1);
        o.z = *reinterpret_cast<uint32_t*>(&h2);
        o.w = *reinterpret_cast<uint32_t*>(&h3);
        reinterpret_cast<uint4*>(xh)[q] = o;
    } else if (bid < NB_X + NB_WQ) {
        int tile = bid - NB_X;
        int bx = tile % (N_QKV / 32);
        int by = tile / (N_QKV / 32);
        transpose_tile(Wqkv, wqkvT, DIM, N_QKV, bx, by, tid);
    } else {
        int tile = bid - NB_X - NB_WQ;
        int bx = tile % (DIM / 32);
        int by = tile / (DIM / 32);
        transpose_tile(Wout, woutT, DIM, DIM, bx, by, tid);
    }
}

// ---------------- anchor attention (one warp per (b,h,s), fp16 QKV) ---------
__global__ __launch_bounds__(256)
void anchor_attn_kernel(const float* __restrict__ gs) {
    const int gw = (blockIdx.x * blockDim.x + threadIdx.x) >> 5;
    const int lane = threadIdx.x & 31;

    const int s = gw % SS;
    const int h = (gw / SS) % NH;
    const int b = gw / (SS * NH);

    const float g0 = gs[0], g1 = gs[1], g2 = gs[2];
    const float mx = fmaxf(g0, fmaxf(g1, g2));
    const float lse = mx + logf(expf(g0 - mx) + expf(g1 - mx) + expf(g2 - mx));
    const float lw0 = g0 - lse, lw1 = g1 - lse, lw2 = g2 - lse;

    const __half* base = g_qkvh + (size_t)b * SS * N_QKV;
    const int hc = h * HD + lane * 4;

    float4 q;
    {
        const __half2* qp = reinterpret_cast<const __half2*>(
            base + (size_t)s * N_QKV + hc);
        float2 a = __half22float2(qp[0]);
        float2 c = __half22float2(qp[1]);
        q = make_float4(a.x, a.y, c.x, c.y);
    }

    int aidx[SIGMA];
    const int offs[10] = {-3, -2, -1, 1, 2, 3, -10, -5, 5, 10};
#pragma unroll
    for (int a = 0; a < 10; a++) {
        int j = s + offs[a];
        aidx[a] = j < 0 ? 0 : (j > SS - 1 ? SS - 1 : j);
    }
    aidx[10] = 0;
    aidx[11] = SS - 1;

    const float scale = 0.08838834764831845f;
    float sc[SIGMA];
#pragma unroll
    for (int a = 0; a < SIGMA; a++) {
        const __half2* kp = reinterpret_cast<const __half2*>(
            base + (size_t)aidx[a] * N_QKV + DIM + hc);
        float2 k0 = __half22float2(kp[0]);
        float2 k1 = __half22float2(kp[1]);
        float d = q.x * k0.x + q.y * k0.y + q.z * k1.x + q.w * k1.y;
#pragma unroll
        for (int o = 16; o > 0; o >>= 1)
            d += __shfl_xor_sync(0xffffffffu, d, o);
        const float lw = (a < 6) ? lw0 : ((a < 10) ? lw1 : lw2);
        sc[a] = d * scale + lw;
    }

    float m = sc[0];
#pragma unroll
    for (int a = 1; a < SIGMA; a++) m = fmaxf(m, sc[a]);
    float sum = 0.0f;
#pragma unroll
    for (int a = 0; a < SIGMA; a++) { sc[a] = __expf(sc[a] - m); sum += sc[a]; }
    const float inv = 1.0f / sum;

    // permuted-chunk dims this lane owns:
    // chunk c = lane>>1 (within head), halfsel = lane&1
    // dims = G*32 + 16*halfsel + 2t + {0,1,8,9}, G = c>>2, t = c&3
    const int cch = lane >> 1;
    const int hs = lane & 1;
    const int d0 = h * HD + (cch >> 2) * 32 + hs * 16 + 2 * (cch & 3);
    float4 acc = make_float4(0.f, 0.f, 0.f, 0.f);
#pragma unroll
    for (int a = 0; a < SIGMA; a++) {
        const float w = sc[a] * inv;
        const __half* vr = base + (size_t)aidx[a] * N_QKV + 2 * DIM + d0;
        float2 v0 = __half22float2(*reinterpret_cast<const __half2*>(vr));
        float2 v1 = __half22float2(*reinterpret_cast<const __half2*>(vr + 8));
        acc.x += w * v0.x; acc.y += w * v0.y;
        acc.z += w * v1.x; acc.w += w * v1.y;
    }

    __half2 p0 = __floats2half2_rn(acc.x, acc.y);
    __half2 p1 = __floats2half2_rn(acc.z, acc.w);
    uint2 o;
    o.x = *reinterpret_cast<uint32_t*>(&p0);
    o.y = *reinterpret_cast<uint32_t*>(&p1);
    *reinterpret_cast<uint2*>(
        g_att + (size_t)(b * SS + s) * DIM + h * HD + cch * 8 + hs * 4) = o;
}

// ---------------------------------------------------------------------------
extern "C" void kernel_launch(void* const* d_in, const int* in_sizes, int n_in,
                              void* d_out, int out_size) {
    const float* x    = (const float*)d_in[0];
    const float* Wqkv = (const float*)d_in[1];
    const float* bqkv = (const float*)d_in[2];
    const float* Wout = (const float*)d_in[3];
    const float* bout = (const float*)d_in[4];
    const float* gsc  = (const float*)d_in[5];
    float* out = (float*)d_out;

    __half *pxh, *pwqkvT, *pwoutT, *patt, *pqkvh;
    cudaGetSymbolAddress((void**)&pxh, g_xh);
    cudaGetSymbolAddress((void**)&pwqkvT, g_wqkvT);
    cudaGetSymbolAddress((void**)&pwoutT, g_woutT);
    cudaGetSymbolAddress((void**)&pqkvh, g_qkvh);
    cudaGetSymbolAddress((void**)&patt, g_att);

    constexpr int SM64 = STAGES * (64 * 128 + BN * 128);   // 73728

    static bool attr_set = false;
    if (!attr_set) {
        cudaFuncSetAttribute((const void*)gemm_f16_mma<64, __half>,
                             cudaFuncAttributeMaxDynamicSharedMemorySize, SM64);
        cudaFuncSetAttribute((const void*)gemm_f16_mma<64, float>,
                             cudaFuncAttributeMaxDynamicSharedMemorySize, SM64);
        attr_set = true;
    }

    // 1) fused pre-pass: x -> permuted fp16; W transposes -> permuted fp16
    prepass_fused<<<NB_X + NB_WQ + NB_WO, 256>>>(x, Wqkv, Wout, pxh, pwqkvT, pwoutT);

    // 2) QKV projection: (4096x1536) @ (1536x4608) -> fp16
    gemm_f16_mma<64, __half><<<dim3(N_QKV / BN, M_TOT / 64), 128, SM64>>>(
        pxh, pwqkvT, bqkv, pqkvh, N_QKV, DIM);

    // 3) anchor attention
    anchor_attn_kernel<<<BB * NH * SS * 32 / 256, 256>>>(gsc);

    // 4) output projection: (4096x1536) @ (1536x1536) -> fp32 out
    gemm_f16_mma<64, float><<<dim3(DIM / BN, M_TOT / 64), 128, SM64>>>(
        patt, pwoutT, bout, out, DIM, DIM);
}

// round 11
// speedup vs baseline: 1.0771x; 1.0428x over previous
#include <cuda_runtime.h>
#include <cuda_fp16.h>
#include <cstdint>
#include <math.h>

#define BB 2
#define SS 2048
#define DIM 1536
#define NH 12
#define HD 128
#define SIGMA 12
#define M_TOT (BB * SS)      // 4096
#define N_QKV (3 * DIM)      // 4608

// ---------------- scratch (__device__ globals; allocation-free rule) -------
__device__ __half g_xh[(size_t)M_TOT * DIM];       // permuted x
__device__ __half g_wqkvT[(size_t)N_QKV * DIM];    // permuted Wqkv^T
__device__ __half g_woutT[(size_t)DIM * DIM];      // permuted Wout^T
__device__ __half g_qkvh[(size_t)M_TOT * N_QKV];   // QKV output (fp16, standard)
__device__ __half g_att[(size_t)M_TOT * DIM];      // attention out (permuted)
__device__ float  g_part[2ull * M_TOT * DIM];      // split-K partials (fp32)

// ---------------- helpers ---------------------------------------------------
__device__ __forceinline__ uint32_t smem_u32(const void* p) {
    uint32_t a;
    asm("{ .reg .u64 t; cvta.to.shared.u64 t, %1; cvt.u32.u64 %0, t; }"
        : "=r"(a) : "l"(p));
    return a;
}
__device__ __forceinline__ void cp16(uint32_t dst, const void* src) {
    asm volatile("cp.async.cg.shared.global [%0], [%1], 16;"
                 :: "r"(dst), "l"(src) : "memory");
}
__device__ __forceinline__ void cp_commit() {
    asm volatile("cp.async.commit_group;" ::: "memory");
}
template <int N>
__device__ __forceinline__ void cp_wait() {
    asm volatile("cp.async.wait_group %0;" :: "n"(N) : "memory");
}
__device__ __forceinline__ void mma_f16(float* c,
                                        uint32_t a0, uint32_t a1, uint32_t a2, uint32_t a3,
                                        uint32_t b0, uint32_t b1) {
    asm("mma.sync.aligned.m16n8k16.row.col.f32.f16.f16.f32 "
        "{%0,%1,%2,%3}, {%4,%5,%6,%7}, {%8,%9}, {%0,%1,%2,%3};"
        : "+f"(c[0]), "+f"(c[1]), "+f"(c[2]), "+f"(c[3])
        : "r"(a0), "r"(a1), "r"(a2), "r"(a3), "r"(b0), "r"(b1));
}
#define F4U(v, i) (reinterpret_cast<const uint32_t*>(&(v))[i])

// ---------------- fp16 GEMM --------------------------------------------------
// A:[M,K] permuted halves, BT:[N,K] permuted halves.
// BMT=128: 4 warps of 64x64 (MT=4), 2 CTAs/SM.  BMT=64: 4 warps of 32x64, 3 CTAs/SM.
// SPLITK: gridDim.z=2, each z does K/2 starting at z*K/2, writes raw partials
// (no bias) to C + z*M_TOT*DIM.
#define BN 128
#define BKH 64               // halves per k-iter (128B rows)
#define STAGES 3

template <int BMT, typename OutT, bool SPLITK, int MBLK>
__global__ __launch_bounds__(128, MBLK)
void gemm_f16_mma(const __half* __restrict__ A, const __half* __restrict__ BT,
                  const float* __restrict__ bias, OutT* __restrict__ C,
                  int Ndim, int K) {
    constexpr int MT = BMT / 32;          // m16 tiles per warp
    constexpr int A_ST = BMT * 128;       // bytes per A stage
    constexpr int B_ST = BN * 128;
    constexpr int STG = A_ST + B_ST;
    extern __shared__ char smem[];
    const uint32_t sbase = smem_u32(smem);

    const int tid = threadIdx.x;
    const int wid = tid >> 5;
    const int lane = tid & 31;
    const int g = lane >> 2;              // 0..7
    const int t = lane & 3;               // 0..3
    const int warp_m = wid >> 1;          // 0..1
    const int warp_n = wid & 1;           // 0..1
    const int m0 = blockIdx.y * BMT;
    const int n0 = blockIdx.x * BN;

    const int Kloc = SPLITK ? (K >> 1) : K;
    const int kbase = SPLITK ? blockIdx.z * Kloc : 0;
    const int KT = Kloc / BKH;
    if (SPLITK) C += (size_t)blockIdx.z * M_TOT * DIM;

    const int lc = tid & 7;               // loader chunk
    const int lr = tid >> 3;              // loader row base (0..15)

    auto load_stage = [&](int stage, int kt) {
        const __half* Ak = A + (size_t)m0 * K + kbase + kt * BKH;
        const __half* Bk = BT + (size_t)n0 * K + kbase + kt * BKH;
        const uint32_t sA = sbase + stage * STG;
        const uint32_t sB = sA + A_ST;
#pragma unroll
        for (int i = 0; i < BMT / 16; i++) {
            int row = i * 16 + lr;
            cp16(sA + row * 128 + (((lc + ((row & 1) << 2)) & 7) << 4),
                 Ak + (size_t)row * K + lc * 8);
        }
#pragma unroll
        for (int i = 0; i < BN / 16; i++) {
            int row = i * 16 + lr;
            cp16(sB + row * 128 + (((lc + ((row & 1) << 2)) & 7) << 4),
                 Bk + (size_t)row * K + lc * 8);
        }
        cp_commit();
    };

    float acc[MT][8][4];
#pragma unroll
    for (int i = 0; i < MT; i++)
#pragma unroll
        for (int j = 0; j < 8; j++)
#pragma unroll
            for (int r = 0; r < 4; r++) acc[i][j][r] = 0.0f;

    load_stage(0, 0);
    load_stage(1, 1);

    const int gp = g & 1;                 // row parity for all fragment rows

    for (int kt = 0; kt < KT; ++kt) {
        cp_wait<1>();
        __syncthreads();
        if (kt + 2 < KT) load_stage((kt + 2) % STAGES, kt + 2);

        const char* sA = smem + (kt % STAGES) * STG;
        const char* sB = sA + A_ST;

#pragma unroll
        for (int h = 0; h < 2; h++) {
            const int ch = t + ((h ^ gp) << 2);   // swizzled chunk, 0..7
            float4 av[MT][2];
#pragma unroll
            for (int mt = 0; mt < MT; mt++)
#pragma unroll
                for (int rr = 0; rr < 2; rr++) {
                    int row = warp_m * (BMT / 2) + mt * 16 + rr * 8 + g;
                    av[mt][rr] = *(const float4*)(sA + row * 128 + ch * 16);
                }
            float4 bv[8];
#pragma unroll
            for (int nt = 0; nt < 8; nt++) {
                int row = warp_n * 64 + nt * 8 + g;
                bv[nt] = *(const float4*)(sB + row * 128 + ch * 16);
            }
#pragma unroll
            for (int mt = 0; mt < MT; mt++)
#pragma unroll
                for (int nt = 0; nt < 8; nt++)
                    mma_f16(acc[mt][nt],
                            F4U(av[mt][0], 0), F4U(av[mt][1], 0),
                            F4U(av[mt][0], 1), F4U(av[mt][1], 1),
                            F4U(bv[nt], 0), F4U(bv[nt], 1));
#pragma unroll
            for (int mt = 0; mt < MT; mt++)
#pragma unroll
                for (int nt = 0; nt < 8; nt++)
                    mma_f16(acc[mt][nt],
                            F4U(av[mt][0], 2), F4U(av[mt][1], 2),
                            F4U(av[mt][0], 3), F4U(av[mt][1], 3),
                            F4U(bv[nt], 2), F4U(bv[nt], 3));
        }
    }

    // epilogue
#pragma unroll
    for (int mt = 0; mt < MT; mt++) {
        const int r0 = m0 + warp_m * (BMT / 2) + mt * 16 + g;
#pragma unroll
        for (int nt = 0; nt < 8; nt++) {
            const int col = n0 + warp_n * 64 + nt * 8 + 2 * t;
            float2 o0, o1;
            if (SPLITK) {                 // raw partials, bias added in reduce
                o0.x = acc[mt][nt][0]; o0.y = acc[mt][nt][1];
                o1.x = acc[mt][nt][2]; o1.y = acc[mt][nt][3];
            } else {
                const float2 bv = *reinterpret_cast<const float2*>(bias + col);
                o0.x = acc[mt][nt][0] + bv.x;
                o0.y = acc[mt][nt][1] + bv.y;
                o1.x = acc[mt][nt][2] + bv.x;
                o1.y = acc[mt][nt][3] + bv.y;
            }
            if constexpr (sizeof(OutT) == 4) {
                float* Cf = (float*)C;
                *reinterpret_cast<float2*>(Cf + (size_t)r0 * Ndim + col) = o0;
                *reinterpret_cast<float2*>(Cf + (size_t)(r0 + 8) * Ndim + col) = o1;
            } else {
                __half* Ch = (__half*)C;
                __half2 h0 = __floats2half2_rn(o0.x, o0.y);
                __half2 h1 = __floats2half2_rn(o1.x, o1.y);
                *reinterpret_cast<__half2*>(Ch + (size_t)r0 * Ndim + col) = h0;
                *reinterpret_cast<__half2*>(Ch + (size_t)(r0 + 8) * Ndim + col) = h1;
            }
        }
    }
}

// ---------------- split-K reduce: out = p0 + p1 + bias ----------------------
__global__ __launch_bounds__(256)
void splitk_reduce(const float* __restrict__ part, const float* __restrict__ bias,
                   float* __restrict__ out) {
    const int i = blockIdx.x * 256 + threadIdx.x;          // float4 index
    const float4 a = reinterpret_cast<const float4*>(part)[i];
    const float4 b = reinterpret_cast<const float4*>(part)[i + M_TOT * DIM / 4];
    const float4 bb = reinterpret_cast<const float4*>(bias)[i % (DIM / 4)];
    float4 o;
    o.x = a.x + b.x + bb.x;
    o.y = a.y + b.y + bb.y;
    o.z = a.z + b.z + bb.z;
    o.w = a.w + b.w + bb.w;
    reinterpret_cast<float4*>(out)[i] = o;
}

// ---------------- fused pre-pass: x perm + both weight transposes -----------
__device__ __forceinline__ void transpose_tile(const float* __restrict__ in,
                                               __half* __restrict__ out,
                                               int R, int C, int bx, int by,
                                               int tid) {
    __shared__ float tbuf[32][33];
    const int tx = tid & 31;
    const int ty = tid >> 5;              // 0..7
#pragma unroll
    for (int i = 0; i < 4; i++) {
        int r = by * 32 + ty + i * 8;
        tbuf[ty + i * 8][tx] = in[(size_t)r * C + bx * 32 + tx];
    }
    __syncthreads();
    const int oc = by * 32 + tx;          // K index
    const int w = oc & 31;
    const int ppos = (oc & ~31) | (((w >> 1) & 3) << 3) | ((w >> 3) << 1) | (w & 1);
#pragma unroll
    for (int i = 0; i < 4; i++) {
        int orow = bx * 32 + ty + i * 8;  // N index
        out[(size_t)orow * R + ppos] = __float2half_rn(tbuf[tx][ty + i * 8]);
    }
}

#define NB_X   (M_TOT * DIM / 8 / 256)          // 3072
#define NB_WQ  ((N_QKV / 32) * (DIM / 32))      // 6912
#define NB_WO  ((DIM / 32) * (DIM / 32))        // 2304

__global__ __launch_bounds__(256)
void prepass_fused(const float* __restrict__ x, const float* __restrict__ Wqkv,
                   const float* __restrict__ Wout,
                   __half* __restrict__ xh, __half* __restrict__ wqkvT,
                   __half* __restrict__ woutT) {
    const int bid = blockIdx.x;
    const int tid = threadIdx.x;
    if (bid < NB_X) {
        int q = bid * 256 + tid;
        int r = q / (DIM / 8);
        int c = q % (DIM / 8);
        int grp = c >> 2, t = c & 3;
        const float* src = x + (size_t)r * DIM + grp * 32 + 2 * t;
        __half2 h0 = __floats2half2_rn(src[0], src[1]);
        __half2 h1 = __floats2half2_rn(src[8], src[9]);
        __half2 h2 = __floats2half2_rn(src[16], src[17]);
        __half2 h3 = __floats2half2_rn(src[24], src[25]);
        uint4 o;
        o.x = *reinterpret_cast<uint32_t*>(&h0);
        o.y = *reinterpret_cast<uint32_t*>(&h1);
        o.z = *reinterpret_cast<uint32_t*>(&h2);
        o.w = *reinterpret_cast<uint32_t*>(&h3);
        reinterpret_cast<uint4*>(xh)[q] = o;
    } else if (bid < NB_X + NB_WQ) {
        int tile = bid - NB_X;
        int bx = tile % (N_QKV / 32);
        int by = tile / (N_QKV / 32);
        transpose_tile(Wqkv, wqkvT, DIM, N_QKV, bx, by, tid);
    } else {
        int tile = bid - NB_X - NB_WQ;
        int bx = tile % (DIM / 32);
        int by = tile / (DIM / 32);
        transpose_tile(Wout, woutT, DIM, DIM, bx, by, tid);
    }
}

// ---------------- anchor attention (one warp per (b,h,s), fp16 QKV) ---------
__global__ __launch_bounds__(256)
void anchor_attn_kernel(const float* __restrict__ gs) {
    const int gw = (blockIdx.x * blockDim.x + threadIdx.x) >> 5;
    const int lane = threadIdx.x & 31;

    const int s = gw % SS;
    const int h = (gw / SS) % NH;
    const int b = gw / (SS * NH);

    const float g0 = gs[0], g1 = gs[1], g2 = gs[2];
    const float mx = fmaxf(g0, fmaxf(g1, g2));
    const float lse = mx + logf(expf(g0 - mx) + expf(g1 - mx) + expf(g2 - mx));
    const float lw0 = g0 - lse, lw1 = g1 - lse, lw2 = g2 - lse;

    const __half* base = g_qkvh + (size_t)b * SS * N_QKV;
    const int hc = h * HD + lane * 4;

    float4 q;
    {
        const __half2* qp = reinterpret_cast<const __half2*>(
            base + (size_t)s * N_QKV + hc);
        float2 a = __half22float2(qp[0]);
        float2 c = __half22float2(qp[1]);
        q = make_float4(a.x, a.y, c.x, c.y);
    }

    int aidx[SIGMA];
    const int offs[10] = {-3, -2, -1, 1, 2, 3, -10, -5, 5, 10};
#pragma unroll
    for (int a = 0; a < 10; a++) {
        int j = s + offs[a];
        aidx[a] = j < 0 ? 0 : (j > SS - 1 ? SS - 1 : j);
    }
    aidx[10] = 0;
    aidx[11] = SS - 1;

    const float scale = 0.08838834764831845f;
    float sc[SIGMA];
#pragma unroll
    for (int a = 0; a < SIGMA; a++) {
        const __half2* kp = reinterpret_cast<const __half2*>(
            base + (size_t)aidx[a] * N_QKV + DIM + hc);
        float2 k0 = __half22float2(kp[0]);
        float2 k1 = __half22float2(kp[1]);
        float d = q.x * k0.x + q.y * k0.y + q.z * k1.x + q.w * k1.y;
#pragma unroll
        for (int o = 16; o > 0; o >>= 1)
            d += __shfl_xor_sync(0xffffffffu, d, o);
        const float lw = (a < 6) ? lw0 : ((a < 10) ? lw1 : lw2);
        sc[a] = d * scale + lw;
    }

    float m = sc[0];
#pragma unroll
    for (int a = 1; a < SIGMA; a++) m = fmaxf(m, sc[a]);
    float sum = 0.0f;
#pragma unroll
    for (int a = 0; a < SIGMA; a++) { sc[a] = __expf(sc[a] - m); sum += sc[a]; }
    const float inv = 1.0f / sum;

    const int cch = lane >> 1;
    const int hs = lane & 1;
    const int d0 = h * HD + (cch >> 2) * 32 + hs * 16 + 2 * (cch & 3);
    float4 acc = make_float4(0.f, 0.f, 0.f, 0.f);
#pragma unroll
    for (int a = 0; a < SIGMA; a++) {
        const float w = sc[a] * inv;
        const __half* vr = base + (size_t)aidx[a] * N_QKV + 2 * DIM + d0;
        float2 v0 = __half22float2(*reinterpret_cast<const __half2*>(vr));
        float2 v1 = __half22float2(*reinterpret_cast<const __half2*>(vr + 8));
        acc.x += w * v0.x; acc.y += w * v0.y;
        acc.z += w * v1.x; acc.w += w * v1.y;
    }

    __half2 p0 = __floats2half2_rn(acc.x, acc.y);
    __half2 p1 = __floats2half2_rn(acc.z, acc.w);
    uint2 o;
    o.x = *reinterpret_cast<uint32_t*>(&p0);
    o.y = *reinterpret_cast<uint32_t*>(&p1);
    *reinterpret_cast<uint2*>(
        g_att + (size_t)(b * SS + s) * DIM + h * HD + cch * 8 + hs * 4) = o;
}

// ---------------------------------------------------------------------------
extern "C" void kernel_launch(void* const* d_in, const int* in_sizes, int n_in,
                              void* d_out, int out_size) {
    const float* x    = (const float*)d_in[0];
    const float* Wqkv = (const float*)d_in[1];
    const float* bqkv = (const float*)d_in[2];
    const float* Wout = (const float*)d_in[3];
    const float* bout = (const float*)d_in[4];
    const float* gsc  = (const float*)d_in[5];
    float* out = (float*)d_out;

    __half *pxh, *pwqkvT, *pwoutT, *patt, *pqkvh;
    float *ppart;
    cudaGetSymbolAddress((void**)&pxh, g_xh);
    cudaGetSymbolAddress((void**)&pwqkvT, g_wqkvT);
    cudaGetSymbolAddress((void**)&pwoutT, g_woutT);
    cudaGetSymbolAddress((void**)&pqkvh, g_qkvh);
    cudaGetSymbolAddress((void**)&patt, g_att);
    cudaGetSymbolAddress((void**)&ppart, g_part);

    constexpr int SM128 = STAGES * (128 * 128 + BN * 128);  // 98304
    constexpr int SM64  = STAGES * (64 * 128 + BN * 128);   // 73728

    static bool attr_set = false;
    if (!attr_set) {
        cudaFuncSetAttribute((const void*)gemm_f16_mma<128, __half, false, 2>,
                             cudaFuncAttributeMaxDynamicSharedMemorySize, SM128);
        cudaFuncSetAttribute((const void*)gemm_f16_mma<64, float, true, 3>,
                             cudaFuncAttributeMaxDynamicSharedMemorySize, SM64);
        attr_set = true;
    }

    // 1) fused pre-pass: x -> permuted fp16; W transposes -> permuted fp16
    prepass_fused<<<NB_X + NB_WQ + NB_WO, 256>>>(x, Wqkv, Wout, pxh, pwqkvT, pwoutT);

    // 2) QKV projection: (4096x1536) @ (1536x4608) -> fp16  (BMT=128, 2 CTAs/SM)
    gemm_f16_mma<128, __half, false, 2>
        <<<dim3(N_QKV / BN, M_TOT / 128), 128, SM128>>>(
        pxh, pwqkvT, bqkv, pqkvh, N_QKV, DIM);

    // 3) anchor attention
    anchor_attn_kernel<<<BB * NH * SS * 32 / 256, 256>>>(gsc);

    // 4) output projection, split-K=2: (4096x1536) @ (1536x1536) -> partials
    gemm_f16_mma<64, float, true, 3>
        <<<dim3(DIM / BN, M_TOT / 64, 2), 128, SM64>>>(
        patt, pwoutT, bout, ppart, DIM, DIM);

    // 5) reduce partials + bias -> fp32 out
    splitk_reduce<<<M_TOT * DIM / 4 / 256, 256>>>(ppart, bout, out);
}

// round 12
// speedup vs baseline: 1.1174x; 1.0375x over previous
#include <cuda_runtime.h>
#include <cuda_fp16.h>
#include <cstdint>
#include <math.h>

#define BB 2
#define SS 2048
#define DIM 1536
#define NH 12
#define HD 128
#define SIGMA 12
#define M_TOT (BB * SS)      // 4096
#define N_QKV (3 * DIM)      // 4608

// ---------------- scratch (__device__ globals; allocation-free rule) -------
__device__ __half g_xh[(size_t)M_TOT * DIM];       // permuted x
__device__ __half g_wqkvT[(size_t)N_QKV * DIM];    // permuted Wqkv^T
__device__ __half g_woutT[(size_t)DIM * DIM];      // permuted Wout^T
__device__ __half g_qkvh[(size_t)M_TOT * N_QKV];   // QKV output (fp16, standard)
__device__ __half g_att[(size_t)M_TOT * DIM];      // attention out (permuted)

// ---------------- helpers ---------------------------------------------------
__device__ __forceinline__ uint32_t smem_u32(const void* p) {
    uint32_t a;
    asm("{ .reg .u64 t; cvta.to.shared.u64 t, %1; cvt.u32.u64 %0, t; }"
        : "=r"(a) : "l"(p));
    return a;
}
__device__ __forceinline__ void cp16(uint32_t dst, const void* src) {
    asm volatile("cp.async.cg.shared.global [%0], [%1], 16;"
                 :: "r"(dst), "l"(src) : "memory");
}
__device__ __forceinline__ void cp_commit() {
    asm volatile("cp.async.commit_group;" ::: "memory");
}
template <int N>
__device__ __forceinline__ void cp_wait() {
    asm volatile("cp.async.wait_group %0;" :: "n"(N) : "memory");
}
__device__ __forceinline__ void mma_f16(float* c,
                                        uint32_t a0, uint32_t a1, uint32_t a2, uint32_t a3,
                                        uint32_t b0, uint32_t b1) {
    asm("mma.sync.aligned.m16n8k16.row.col.f32.f16.f16.f32 "
        "{%0,%1,%2,%3}, {%4,%5,%6,%7}, {%8,%9}, {%0,%1,%2,%3};"
        : "+f"(c[0]), "+f"(c[1]), "+f"(c[2]), "+f"(c[3])
        : "r"(a0), "r"(a1), "r"(a2), "r"(a3), "r"(b0), "r"(b1));
}
#define F4U(v, i) (reinterpret_cast<const uint32_t*>(&(v))[i])

// ---------------- fp16 GEMM: CTA 128x128, 4 warps of 64x64, 2 CTAs/SM -------
// A:[M,K] permuted halves, BT:[N,K] permuted halves, C standard (OutT).
#define BN 128
#define BMT 128
#define BKH 64               // halves per k-iter (128B rows)
#define STAGES 3

template <typename OutT>
__global__ __launch_bounds__(128, 2)
void gemm_f16_mma(const __half* __restrict__ A, const __half* __restrict__ BT,
                  const float* __restrict__ bias, OutT* __restrict__ C,
                  int Ndim, int K) {
    constexpr int MT = BMT / 32;          // 4 m16 tiles per warp
    constexpr int A_ST = BMT * 128;       // bytes per A stage
    constexpr int B_ST = BN * 128;
    constexpr int STG = A_ST + B_ST;
    extern __shared__ char smem[];
    const uint32_t sbase = smem_u32(smem);

    const int tid = threadIdx.x;
    const int wid = tid >> 5;
    const int lane = tid & 31;
    const int g = lane >> 2;              // 0..7
    const int t = lane & 3;               // 0..3
    const int warp_m = wid >> 1;          // 0..1
    const int warp_n = wid & 1;           // 0..1
    const int m0 = blockIdx.y * BMT;
    const int n0 = blockIdx.x * BN;
    const int KT = K / BKH;

    const int lc = tid & 7;               // loader chunk
    const int lr = tid >> 3;              // loader row base (0..15)

    auto load_stage = [&](int stage, int kt) {
        const __half* Ak = A + (size_t)m0 * K + kt * BKH;
        const __half* Bk = BT + (size_t)n0 * K + kt * BKH;
        const uint32_t sA = sbase + stage * STG;
        const uint32_t sB = sA + A_ST;
#pragma unroll
        for (int i = 0; i < BMT / 16; i++) {
            int row = i * 16 + lr;
            cp16(sA + row * 128 + (((lc + ((row & 1) << 2)) & 7) << 4),
                 Ak + (size_t)row * K + lc * 8);
        }
#pragma unroll
        for (int i = 0; i < BN / 16; i++) {
            int row = i * 16 + lr;
            cp16(sB + row * 128 + (((lc + ((row & 1) << 2)) & 7) << 4),
                 Bk + (size_t)row * K + lc * 8);
        }
        cp_commit();
    };

    float acc[MT][8][4];
#pragma unroll
    for (int i = 0; i < MT; i++)
#pragma unroll
        for (int j = 0; j < 8; j++)
#pragma unroll
            for (int r = 0; r < 4; r++) acc[i][j][r] = 0.0f;

    load_stage(0, 0);
    load_stage(1, 1);

    const int gp = g & 1;                 // row parity for all fragment rows

    for (int kt = 0; kt < KT; ++kt) {
        cp_wait<1>();
        __syncthreads();
        if (kt + 2 < KT) load_stage((kt + 2) % STAGES, kt + 2);

        const char* sA = smem + (kt % STAGES) * STG;
        const char* sB = sA + A_ST;

#pragma unroll
        for (int h = 0; h < 2; h++) {
            const int ch = t + ((h ^ gp) << 2);   // swizzled chunk, 0..7
            float4 av[MT][2];
#pragma unroll
            for (int mt = 0; mt < MT; mt++)
#pragma unroll
                for (int rr = 0; rr < 2; rr++) {
                    int row = warp_m * (BMT / 2) + mt * 16 + rr * 8 + g;
                    av[mt][rr] = *(const float4*)(sA + row * 128 + ch * 16);
                }
            float4 bv[8];
#pragma unroll
            for (int nt = 0; nt < 8; nt++) {
                int row = warp_n * 64 + nt * 8 + g;
                bv[nt] = *(const float4*)(sB + row * 128 + ch * 16);
            }
#pragma unroll
            for (int mt = 0; mt < MT; mt++)
#pragma unroll
                for (int nt = 0; nt < 8; nt++)
                    mma_f16(acc[mt][nt],
                            F4U(av[mt][0], 0), F4U(av[mt][1], 0),
                            F4U(av[mt][0], 1), F4U(av[mt][1], 1),
                            F4U(bv[nt], 0), F4U(bv[nt], 1));
#pragma unroll
            for (int mt = 0; mt < MT; mt++)
#pragma unroll
                for (int nt = 0; nt < 8; nt++)
                    mma_f16(acc[mt][nt],
                            F4U(av[mt][0], 2), F4U(av[mt][1], 2),
                            F4U(av[mt][0], 3), F4U(av[mt][1], 3),
                            F4U(bv[nt], 2), F4U(bv[nt], 3));
        }
    }

    // epilogue: bias in fp32, output fp32 or fp16
#pragma unroll
    for (int mt = 0; mt < MT; mt++) {
        const int r0 = m0 + warp_m * (BMT / 2) + mt * 16 + g;
#pragma unroll
        for (int nt = 0; nt < 8; nt++) {
            const int col = n0 + warp_n * 64 + nt * 8 + 2 * t;
            const float2 bv = *reinterpret_cast<const float2*>(bias + col);
            float2 o0, o1;
            o0.x = acc[mt][nt][0] + bv.x;
            o0.y = acc[mt][nt][1] + bv.y;
            o1.x = acc[mt][nt][2] + bv.x;
            o1.y = acc[mt][nt][3] + bv.y;
            if constexpr (sizeof(OutT) == 4) {
                float* Cf = (float*)C;
                *reinterpret_cast<float2*>(Cf + (size_t)r0 * Ndim + col) = o0;
                *reinterpret_cast<float2*>(Cf + (size_t)(r0 + 8) * Ndim + col) = o1;
            } else {
                __half* Ch = (__half*)C;
                __half2 h0 = __floats2half2_rn(o0.x, o0.y);
                __half2 h1 = __floats2half2_rn(o1.x, o1.y);
                *reinterpret_cast<__half2*>(Ch + (size_t)r0 * Ndim + col) = h0;
                *reinterpret_cast<__half2*>(Ch + (size_t)(r0 + 8) * Ndim + col) = h1;
            }
        }
    }
}

// ---------------- fused pre-pass: x perm + both weight transposes -----------
__device__ __forceinline__ void transpose_tile(const float* __restrict__ in,
                                               __half* __restrict__ out,
                                               int R, int C, int bx, int by,
                                               int tid) {
    __shared__ float tbuf[32][33];
    const int tx = tid & 31;
    const int ty = tid >> 5;              // 0..7
#pragma unroll
    for (int i = 0; i < 4; i++) {
        int r = by * 32 + ty + i * 8;
        tbuf[ty + i * 8][tx] = in[(size_t)r * C + bx * 32 + tx];
    }
    __syncthreads();
    const int oc = by * 32 + tx;          // K index
    const int w = oc & 31;
    const int ppos = (oc & ~31) | (((w >> 1) & 3) << 3) | ((w >> 3) << 1) | (w & 1);
#pragma unroll
    for (int i = 0; i < 4; i++) {
        int orow = bx * 32 + ty + i * 8;  // N index
        out[(size_t)orow * R + ppos] = __float2half_rn(tbuf[tx][ty + i * 8]);
    }
}

#define NB_X   (M_TOT * DIM / 8 / 256)          // 3072
#define NB_WQ  ((N_QKV / 32) * (DIM / 32))      // 6912
#define NB_WO  ((DIM / 32) * (DIM / 32))        // 2304

__global__ __launch_bounds__(256)
void prepass_fused(const float* __restrict__ x, const float* __restrict__ Wqkv,
                   const float* __restrict__ Wout,
                   __half* __restrict__ xh, __half* __restrict__ wqkvT,
                   __half* __restrict__ woutT) {
    const int bid = blockIdx.x;
    const int tid = threadIdx.x;
    if (bid < NB_X) {
        int q = bid * 256 + tid;
        int r = q / (DIM / 8);
        int c = q % (DIM / 8);
        int grp = c >> 2, t = c & 3;
        const float* src = x + (size_t)r * DIM + grp * 32 + 2 * t;
        __half2 h0 = __floats2half2_rn(src[0], src[1]);
        __half2 h1 = __floats2half2_rn(src[8], src[9]);
        __half2 h2 = __floats2half2_rn(src[16], src[17]);
        __half2 h3 = __floats2half2_rn(src[24], src[25]);
        uint4 o;
        o.x = *reinterpret_cast<uint32_t*>(&h0);
        o.y = *reinterpret_cast<uint32_t*>(&h1);
        o.z = *reinterpret_cast<uint32_t*>(&h2);
        o.w = *reinterpret_cast<uint32_t*>(&h3);
        reinterpret_cast<uint4*>(xh)[q] = o;
    } else if (bid < NB_X + NB_WQ) {
        int tile = bid - NB_X;
        int bx = tile % (N_QKV / 32);
        int by = tile / (N_QKV / 32);
        transpose_tile(Wqkv, wqkvT, DIM, N_QKV, bx, by, tid);
    } else {
        int tile = bid - NB_X - NB_WQ;
        int bx = tile % (DIM / 32);
        int by = tile / (DIM / 32);
        transpose_tile(Wout, woutT, DIM, DIM, bx, by, tid);
    }
}

// ---------------- anchor attention (one warp per (b,h,s), fp16 QKV) ---------
__global__ __launch_bounds__(256)
void anchor_attn_kernel(const float* __restrict__ gs) {
    const int gw = (blockIdx.x * blockDim.x + threadIdx.x) >> 5;
    const int lane = threadIdx.x & 31;

    const int s = gw % SS;
    const int h = (gw / SS) % NH;
    const int b = gw / (SS * NH);

    const float g0 = gs[0], g1 = gs[1], g2 = gs[2];
    const float mx = fmaxf(g0, fmaxf(g1, g2));
    const float lse = mx + logf(expf(g0 - mx) + expf(g1 - mx) + expf(g2 - mx));
    const float lw0 = g0 - lse, lw1 = g1 - lse, lw2 = g2 - lse;

    const __half* base = g_qkvh + (size_t)b * SS * N_QKV;
    const int hc = h * HD + lane * 4;

    float4 q;
    {
        const __half2* qp = reinterpret_cast<const __half2*>(
            base + (size_t)s * N_QKV + hc);
        float2 a = __half22float2(qp[0]);
        float2 c = __half22float2(qp[1]);
        q = make_float4(a.x, a.y, c.x, c.y);
    }

    int aidx[SIGMA];
    const int offs[10] = {-3, -2, -1, 1, 2, 3, -10, -5, 5, 10};
#pragma unroll
    for (int a = 0; a < 10; a++) {
        int j = s + offs[a];
        aidx[a] = j < 0 ? 0 : (j > SS - 1 ? SS - 1 : j);
    }
    aidx[10] = 0;
    aidx[11] = SS - 1;

    const float scale = 0.08838834764831845f;
    float sc[SIGMA];
#pragma unroll
    for (int a = 0; a < SIGMA; a++) {
        const __half2* kp = reinterpret_cast<const __half2*>(
            base + (size_t)aidx[a] * N_QKV + DIM + hc);
        float2 k0 = __half22float2(kp[0]);
        float2 k1 = __half22float2(kp[1]);
        float d = q.x * k0.x + q.y * k0.y + q.z * k1.x + q.w * k1.y;
#pragma unroll
        for (int o = 16; o > 0; o >>= 1)
            d += __shfl_xor_sync(0xffffffffu, d, o);
        const float lw = (a < 6) ? lw0 : ((a < 10) ? lw1 : lw2);
        sc[a] = d * scale + lw;
    }

    float m = sc[0];
#pragma unroll
    for (int a = 1; a < SIGMA; a++) m = fmaxf(m, sc[a]);
    float sum = 0.0f;
#pragma unroll
    for (int a = 0; a < SIGMA; a++) { sc[a] = __expf(sc[a] - m); sum += sc[a]; }
    const float inv = 1.0f / sum;

    const int cch = lane >> 1;
    const int hs = lane & 1;
    const int d0 = h * HD + (cch >> 2) * 32 + hs * 16 + 2 * (cch & 3);
    float4 acc = make_float4(0.f, 0.f, 0.f, 0.f);
#pragma unroll
    for (int a = 0; a < SIGMA; a++) {
        const float w = sc[a] * inv;
        const __half* vr = base + (size_t)aidx[a] * N_QKV + 2 * DIM + d0;
        float2 v0 = __half22float2(*reinterpret_cast<const __half2*>(vr));
        float2 v1 = __half22float2(*reinterpret_cast<const __half2*>(vr + 8));
        acc.x += w * v0.x; acc.y += w * v0.y;
        acc.z += w * v1.x; acc.w += w * v1.y;
    }

    __half2 p0 = __floats2half2_rn(acc.x, acc.y);
    __half2 p1 = __floats2half2_rn(acc.z, acc.w);
    uint2 o;
    o.x = *reinterpret_cast<uint32_t*>(&p0);
    o.y = *reinterpret_cast<uint32_t*>(&p1);
    *reinterpret_cast<uint2*>(
        g_att + (size_t)(b * SS + s) * DIM + h * HD + cch * 8 + hs * 4) = o;
}

// ---------------------------------------------------------------------------
extern "C" void kernel_launch(void* const* d_in, const int* in_sizes, int n_in,
                              void* d_out, int out_size) {
    const float* x    = (const float*)d_in[0];
    const float* Wqkv = (const float*)d_in[1];
    const float* bqkv = (const float*)d_in[2];
    const float* Wout = (const float*)d_in[3];
    const float* bout = (const float*)d_in[4];
    const float* gsc  = (const float*)d_in[5];
    float* out = (float*)d_out;

    __half *pxh, *pwqkvT, *pwoutT, *patt, *pqkvh;
    cudaGetSymbolAddress((void**)&pxh, g_xh);
    cudaGetSymbolAddress((void**)&pwqkvT, g_wqkvT);
    cudaGetSymbolAddress((void**)&pwoutT, g_woutT);
    cudaGetSymbolAddress((void**)&pqkvh, g_qkvh);
    cudaGetSymbolAddress((void**)&patt, g_att);

    constexpr int SM128 = STAGES * (BMT * 128 + BN * 128);  // 98304

    static bool attr_set = false;
    if (!attr_set) {
        cudaFuncSetAttribute((const void*)gemm_f16_mma<__half>,
                             cudaFuncAttributeMaxDynamicSharedMemorySize, SM128);
        cudaFuncSetAttribute((const void*)gemm_f16_mma<float>,
                             cudaFuncAttributeMaxDynamicSharedMemorySize, SM128);
        attr_set = true;
    }

    // 1) fused pre-pass: x -> permuted fp16; W transposes -> permuted fp16
    prepass_fused<<<NB_X + NB_WQ + NB_WO, 256>>>(x, Wqkv, Wout, pxh, pwqkvT, pwoutT);

    // 2) QKV projection: (4096x1536) @ (1536x4608) -> fp16
    gemm_f16_mma<__half><<<dim3(N_QKV / BN, M_TOT / BMT), 128, SM128>>>(
        pxh, pwqkvT, bqkv, pqkvh, N_QKV, DIM);

    // 3) anchor attention
    anchor_attn_kernel<<<BB * NH * SS * 32 / 256, 256>>>(gsc);

    // 4) output projection: (4096x1536) @ (1536x1536) -> fp32 out
    gemm_f16_mma<float><<<dim3(DIM / BN, M_TOT / BMT), 128, SM128>>>(
        patt, pwoutT, bout, out, DIM, DIM);
}

// round 14
// speedup vs baseline: 1.1185x; 1.0009x over previous
#include <cuda_runtime.h>
#include <cuda_fp16.h>
#include <cstdint>
#include <math.h>

#define BB 2
#define SS 2048
#define DIM 1536
#define NH 12
#define HD 128
#define SIGMA 12
#define M_TOT (BB * SS)      // 4096
#define N_QKV (3 * DIM)      // 4608
#define M_HALF (M_TOT / 2)   // 2048 rows per batch

// ---------------- scratch (__device__ globals; allocation-free rule) -------
__device__ __half g_xh[(size_t)M_TOT * DIM];       // permuted x
__device__ __half g_wqkvT[(size_t)N_QKV * DIM];    // permuted Wqkv^T
__device__ __half g_woutT[(size_t)DIM * DIM];      // permuted Wout^T
__device__ __half g_qkvh[(size_t)M_TOT * N_QKV];   // QKV output (fp16, standard)
__device__ __half g_att[(size_t)M_TOT * DIM];      // attention out (permuted)

// ---------------- helpers ---------------------------------------------------
__device__ __forceinline__ uint32_t smem_u32(const void* p) {
    uint32_t a;
    asm("{ .reg .u64 t; cvta.to.shared.u64 t, %1; cvt.u32.u64 %0, t; }"
        : "=r"(a) : "l"(p));
    return a;
}
__device__ __forceinline__ void cp16(uint32_t dst, const void* src) {
    asm volatile("cp.async.cg.shared.global [%0], [%1], 16;"
                 :: "r"(dst), "l"(src) : "memory");
}
__device__ __forceinline__ void cp_commit() {
    asm volatile("cp.async.commit_group;" ::: "memory");
}
template <int N>
__device__ __forceinline__ void cp_wait() {
    asm volatile("cp.async.wait_group %0;" :: "n"(N) : "memory");
}
__device__ __forceinline__ void mma_f16(float* c,
                                        uint32_t a0, uint32_t a1, uint32_t a2, uint32_t a3,
                                        uint32_t b0, uint32_t b1) {
    asm("mma.sync.aligned.m16n8k16.row.col.f32.f16.f16.f32 "
        "{%0,%1,%2,%3}, {%4,%5,%6,%7}, {%8,%9}, {%0,%1,%2,%3};"
        : "+f"(c[0]), "+f"(c[1]), "+f"(c[2]), "+f"(c[3])
        : "r"(a0), "r"(a1), "r"(a2), "r"(a3), "r"(b0), "r"(b1));
}
#define F4U(v, i) (reinterpret_cast<const uint32_t*>(&(v))[i])

// ---------------- fp16 GEMM: CTA 128x128, 4 warps of 64x64, 2 CTAs/SM -------
#define BN 128
#define BMT 128
#define BKH 64               // halves per k-iter (128B rows)
#define STAGES 3

template <typename OutT>
__global__ __launch_bounds__(128, 2)
void gemm_f16_mma(const __half* __restrict__ A, const __half* __restrict__ BT,
                  const float* __restrict__ bias, OutT* __restrict__ C,
                  int Ndim, int K) {
    constexpr int MT = BMT / 32;          // 4 m16 tiles per warp
    constexpr int A_ST = BMT * 128;       // bytes per A stage
    constexpr int B_ST = BN * 128;
    constexpr int STG = A_ST + B_ST;
    extern __shared__ char smem[];
    const uint32_t sbase = smem_u32(smem);

    const int tid = threadIdx.x;
    const int wid = tid >> 5;
    const int lane = tid & 31;
    const int g = lane >> 2;              // 0..7
    const int t = lane & 3;               // 0..3
    const int warp_m = wid >> 1;          // 0..1
    const int warp_n = wid & 1;           // 0..1
    const int m0 = blockIdx.y * BMT;
    const int n0 = blockIdx.x * BN;
    const int KT = K / BKH;

    const int lc = tid & 7;               // loader chunk
    const int lr = tid >> 3;              // loader row base (0..15)

    auto load_stage = [&](int stage, int kt) {
        const __half* Ak = A + (size_t)m0 * K + kt * BKH;
        const __half* Bk = BT + (size_t)n0 * K + kt * BKH;
        const uint32_t sA = sbase + stage * STG;
        const uint32_t sB = sA + A_ST;
#pragma unroll
        for (int i = 0; i < BMT / 16; i++) {
            int row = i * 16 + lr;
            cp16(sA + row * 128 + (((lc + ((row & 1) << 2)) & 7) << 4),
                 Ak + (size_t)row * K + lc * 8);
        }
#pragma unroll
        for (int i = 0; i < BN / 16; i++) {
            int row = i * 16 + lr;
            cp16(sB + row * 128 + (((lc + ((row & 1) << 2)) & 7) << 4),
                 Bk + (size_t)row * K + lc * 8);
        }
        cp_commit();
    };

    float acc[MT][8][4];
#pragma unroll
    for (int i = 0; i < MT; i++)
#pragma unroll
        for (int j = 0; j < 8; j++)
#pragma unroll
            for (int r = 0; r < 4; r++) acc[i][j][r] = 0.0f;

    load_stage(0, 0);
    load_stage(1, 1);

    const int gp = g & 1;                 // row parity for all fragment rows

    for (int kt = 0; kt < KT; ++kt) {
        cp_wait<1>();
        __syncthreads();
        if (kt + 2 < KT) load_stage((kt + 2) % STAGES, kt + 2);

        const char* sA = smem + (kt % STAGES) * STG;
        const char* sB = sA + A_ST;

#pragma unroll
        for (int h = 0; h < 2; h++) {
            const int ch = t + ((h ^ gp) << 2);   // swizzled chunk, 0..7
            float4 av[MT][2];
#pragma unroll
            for (int mt = 0; mt < MT; mt++)
#pragma unroll
                for (int rr = 0; rr < 2; rr++) {
                    int row = warp_m * (BMT / 2) + mt * 16 + rr * 8 + g;
                    av[mt][rr] = *(const float4*)(sA + row * 128 + ch * 16);
                }
            float4 bv[8];
#pragma unroll
            for (int nt = 0; nt < 8; nt++) {
                int row = warp_n * 64 + nt * 8 + g;
                bv[nt] = *(const float4*)(sB + row * 128 + ch * 16);
            }
#pragma unroll
            for (int mt = 0; mt < MT; mt++)
#pragma unroll
                for (int nt = 0; nt < 8; nt++)
                    mma_f16(acc[mt][nt],
                            F4U(av[mt][0], 0), F4U(av[mt][1], 0),
                            F4U(av[mt][0], 1), F4U(av[mt][1], 1),
                            F4U(bv[nt], 0), F4U(bv[nt], 1));
#pragma unroll
            for (int mt = 0; mt < MT; mt++)
#pragma unroll
                for (int nt = 0; nt < 8; nt++)
                    mma_f16(acc[mt][nt],
                            F4U(av[mt][0], 2), F4U(av[mt][1], 2),
                            F4U(av[mt][0], 3), F4U(av[mt][1], 3),
                            F4U(bv[nt], 2), F4U(bv[nt], 3));
        }
    }

    // epilogue: bias in fp32, output fp32 or fp16
#pragma unroll
    for (int mt = 0; mt < MT; mt++) {
        const int r0 = m0 + warp_m * (BMT / 2) + mt * 16 + g;
#pragma unroll
        for (int nt = 0; nt < 8; nt++) {
            const int col = n0 + warp_n * 64 + nt * 8 + 2 * t;
            const float2 bv = *reinterpret_cast<const float2*>(bias + col);
            float2 o0, o1;
            o0.x = acc[mt][nt][0] + bv.x;
            o0.y = acc[mt][nt][1] + bv.y;
            o1.x = acc[mt][nt][2] + bv.x;
            o1.y = acc[mt][nt][3] + bv.y;
            if constexpr (sizeof(OutT) == 4) {
                float* Cf = (float*)C;
                *reinterpret_cast<float2*>(Cf + (size_t)r0 * Ndim + col) = o0;
                *reinterpret_cast<float2*>(Cf + (size_t)(r0 + 8) * Ndim + col) = o1;
            } else {
                __half* Ch = (__half*)C;
                __half2 h0 = __floats2half2_rn(o0.x, o0.y);
                __half2 h1 = __floats2half2_rn(o1.x, o1.y);
                *reinterpret_cast<__half2*>(Ch + (size_t)r0 * Ndim + col) = h0;
                *reinterpret_cast<__half2*>(Ch + (size_t)(r0 + 8) * Ndim + col) = h1;
            }
        }
    }
}

// ---------------- pre-pass kernels ------------------------------------------
__device__ __forceinline__ void transpose_tile(const float* __restrict__ in,
                                               __half* __restrict__ out,
                                               int R, int C, int bx, int by,
                                               int tid) {
    __shared__ float tbuf[32][33];
    const int tx = tid & 31;
    const int ty = tid >> 5;              // 0..7
#pragma unroll
    for (int i = 0; i < 4; i++) {
        int r = by * 32 + ty + i * 8;
        tbuf[ty + i * 8][tx] = in[(size_t)r * C + bx * 32 + tx];
    }
    __syncthreads();
    const int oc = by * 32 + tx;          // K index
    const int w = oc & 31;
    const int ppos = (oc & ~31) | (((w >> 1) & 3) << 3) | ((w >> 3) << 1) | (w & 1);
#pragma unroll
    for (int i = 0; i < 4; i++) {
        int orow = bx * 32 + ty + i * 8;  // N index
        out[(size_t)orow * R + ppos] = __float2half_rn(tbuf[tx][ty + i * 8]);
    }
}

#define NB_X   (M_TOT * DIM / 8 / 256)          // 3072
#define NB_WQ  ((N_QKV / 32) * (DIM / 32))      // 6912
#define NB_WO  ((DIM / 32) * (DIM / 32))        // 2304

// x-perm + WqkvT (needed before GEMM1)
__global__ __launch_bounds__(256)
void prepass_main(const float* __restrict__ x, const float* __restrict__ Wqkv,
                  __half* __restrict__ xh, __half* __restrict__ wqkvT) {
    const int bid = blockIdx.x;
    const int tid = threadIdx.x;
    if (bid < NB_X) {
        int q = bid * 256 + tid;
        int r = q / (DIM / 8);
        int c = q % (DIM / 8);
        int grp = c >> 2, t = c & 3;
        const float* src = x + (size_t)r * DIM + grp * 32 + 2 * t;
        __half2 h0 = __floats2half2_rn(src[0], src[1]);
        __half2 h1 = __floats2half2_rn(src[8], src[9]);
        __half2 h2 = __floats2half2_rn(src[16], src[17]);
        __half2 h3 = __floats2half2_rn(src[24], src[25]);
        uint4 o;
        o.x = *reinterpret_cast<uint32_t*>(&h0);
        o.y = *reinterpret_cast<uint32_t*>(&h1);
        o.z = *reinterpret_cast<uint32_t*>(&h2);
        o.w = *reinterpret_cast<uint32_t*>(&h3);
        reinterpret_cast<uint4*>(xh)[q] = o;
    } else {
        int tile = bid - NB_X;
        int bx = tile % (N_QKV / 32);
        int by = tile / (N_QKV / 32);
        transpose_tile(Wqkv, wqkvT, DIM, N_QKV, bx, by, tid);
    }
}

// WoutT (needed only before GEMM2) — runs on side stream, overlaps GEMM1
__global__ __launch_bounds__(256)
void prepass_wout(const float* __restrict__ Wout, __half* __restrict__ woutT) {
    const int tile = blockIdx.x;
    const int bx = tile % (DIM / 32);
    const int by = tile / (DIM / 32);
    transpose_tile(Wout, woutT, DIM, DIM, bx, by, threadIdx.x);
}

// ---------------- anchor attention (one warp per (h,s) of one batch) --------
__global__ __launch_bounds__(256)
void anchor_attn_kernel(const float* __restrict__ gs, int batch) {
    const int gw = (blockIdx.x * blockDim.x + threadIdx.x) >> 5;
    const int lane = threadIdx.x & 31;

    const int s = gw % SS;
    const int h = gw / SS;                // 0..NH-1
    const int b = batch;

    const float g0 = gs[0], g1 = gs[1], g2 = gs[2];
    const float mx = fmaxf(g0, fmaxf(g1, g2));
    const float lse = mx + logf(expf(g0 - mx) + expf(g1 - mx) + expf(g2 - mx));
    const float lw0 = g0 - lse, lw1 = g1 - lse, lw2 = g2 - lse;

    const __half* base = g_qkvh + (size_t)b * SS * N_QKV;
    const int hc = h * HD + lane * 4;

    float4 q;
    {
        const __half2* qp = reinterpret_cast<const __half2*>(
            base + (size_t)s * N_QKV + hc);
        float2 a = __half22float2(qp[0]);
        float2 c = __half22float2(qp[1]);
        q = make_float4(a.x, a.y, c.x, c.y);
    }

    int aidx[SIGMA];
    const int offs[10] = {-3, -2, -1, 1, 2, 3, -10, -5, 5, 10};
#pragma unroll
    for (int a = 0; a < 10; a++) {
        int j = s + offs[a];
        aidx[a] = j < 0 ? 0 : (j > SS - 1 ? SS - 1 : j);
    }
    aidx[10] = 0;
    aidx[11] = SS - 1;

    const float scale = 0.08838834764831845f;
    float sc[SIGMA];
#pragma unroll
    for (int a = 0; a < SIGMA; a++) {
        const __half2* kp = reinterpret_cast<const __half2*>(
            base + (size_t)aidx[a] * N_QKV + DIM + hc);
        float2 k0 = __half22float2(kp[0]);
        float2 k1 = __half22float2(kp[1]);
        float d = q.x * k0.x + q.y * k0.y + q.z * k1.x + q.w * k1.y;
#pragma unroll
        for (int o = 16; o > 0; o >>= 1)
            d += __shfl_xor_sync(0xffffffffu, d, o);
        const float lw = (a < 6) ? lw0 : ((a < 10) ? lw1 : lw2);
        sc[a] = d * scale + lw;
    }

    float m = sc[0];
#pragma unroll
    for (int a = 1; a < SIGMA; a++) m = fmaxf(m, sc[a]);
    float sum = 0.0f;
#pragma unroll
    for (int a = 0; a < SIGMA; a++) { sc[a] = __expf(sc[a] - m); sum += sc[a]; }
    const float inv = 1.0f / sum;

    const int cch = lane >> 1;
    const int hs = lane & 1;
    const int d0 = h * HD + (cch >> 2) * 32 + hs * 16 + 2 * (cch & 3);
    float4 acc = make_float4(0.f, 0.f, 0.f, 0.f);
#pragma unroll
    for (int a = 0; a < SIGMA; a++) {
        const float w = sc[a] * inv;
        const __half* vr = base + (size_t)aidx[a] * N_QKV + 2 * DIM + d0;
        float2 v0 = __half22float2(*reinterpret_cast<const __half2*>(vr));
        float2 v1 = __half22float2(*reinterpret_cast<const __half2*>(vr + 8));
        acc.x += w * v0.x; acc.y += w * v0.y;
        acc.z += w * v1.x; acc.w += w * v1.y;
    }

    __half2 p0 = __floats2half2_rn(acc.x, acc.y);
    __half2 p1 = __floats2half2_rn(acc.z, acc.w);
    uint2 o;
    o.x = *reinterpret_cast<uint32_t*>(&p0);
    o.y = *reinterpret_cast<uint32_t*>(&p1);
    *reinterpret_cast<uint2*>(
        g_att + (size_t)(b * SS + s) * DIM + h * HD + cch * 8 + hs * 4) = o;
}

// ---------------------------------------------------------------------------
extern "C" void kernel_launch(void* const* d_in, const int* in_sizes, int n_in,
                              void* d_out, int out_size) {
    const float* x    = (const float*)d_in[0];
    const float* Wqkv = (const float*)d_in[1];
    const float* bqkv = (const float*)d_in[2];
    const float* Wout = (const float*)d_in[3];
    const float* bout = (const float*)d_in[4];
    const float* gsc  = (const float*)d_in[5];
    float* out = (float*)d_out;

    __half *pxh, *pwqkvT, *pwoutT, *patt, *pqkvh;
    cudaGetSymbolAddress((void**)&pxh, g_xh);
    cudaGetSymbolAddress((void**)&pwqkvT, g_wqkvT);
    cudaGetSymbolAddress((void**)&pwoutT, g_woutT);
    cudaGetSymbolAddress((void**)&pqkvh, g_qkvh);
    cudaGetSymbolAddress((void**)&patt, g_att);

    constexpr int SM128 = STAGES * (BMT * 128 + BN * 128);  // 98304

    static cudaStream_t s1;
    static cudaEvent_t ev0, evW, evB, evD;
    static bool init_done = false;
    if (!init_done) {
        cudaFuncSetAttribute((const void*)gemm_f16_mma<__half>,
                             cudaFuncAttributeMaxDynamicSharedMemorySize, SM128);
        cudaFuncSetAttribute((const void*)gemm_f16_mma<float>,
                             cudaFuncAttributeMaxDynamicSharedMemorySize, SM128);
        cudaStreamCreateWithFlags(&s1, cudaStreamNonBlocking);
        cudaEventCreateWithFlags(&ev0, cudaEventDisableTiming);
        cudaEventCreateWithFlags(&evW, cudaEventDisableTiming);
        cudaEventCreateWithFlags(&evB, cudaEventDisableTiming);
        cudaEventCreateWithFlags(&evD, cudaEventDisableTiming);
        init_done = true;
    }

    const int attn_blocks = NH * SS * 32 / 256;   // 3072 per batch

    // fork side stream at entry
    cudaEventRecord(ev0, 0);
    cudaStreamWaitEvent(s1, ev0, 0);

    // s1: WoutT transpose (independent; overlaps prepass_main + GEMM1)
    prepass_wout<<<NB_WO, 256, 0, s1>>>(Wout, pwoutT);
    cudaEventRecord(evW, s1);

    // s0: x-perm + WqkvT, then GEMM1 for batch 0
    prepass_main<<<NB_X + NB_WQ, 256>>>(x, Wqkv, pxh, pwqkvT);
    gemm_f16_mma<__half><<<dim3(N_QKV / BN, M_HALF / BMT), 128, SM128>>>(
        pxh, pwqkvT, bqkv, pqkvh, N_QKV, DIM);
    cudaEventRecord(evB, 0);

    // s1: GEMM1 for batch 1 (after GEMM1 b0 completes)
    cudaStreamWaitEvent(s1, evB, 0);
    gemm_f16_mma<__half><<<dim3(N_QKV / BN, M_HALF / BMT), 128, SM128, s1>>>(
        pxh + (size_t)M_HALF * DIM, pwqkvT, bqkv,
        pqkvh + (size_t)M_HALF * N_QKV, N_QKV, DIM);

    // s0: attention b0 (overlaps GEMM1 b1)
    anchor_attn_kernel<<<attn_blocks, 256>>>(gsc, 0);

    // s1: attention b1
    anchor_attn_kernel<<<attn_blocks, 256, 0, s1>>>(gsc, 1);

    // s0: GEMM2 b0 (needs WoutT from s1)
    cudaStreamWaitEvent(0, evW, 0);
    gemm_f16_mma<float><<<dim3(DIM / BN, M_HALF / BMT), 128, SM128>>>(
        patt, pwoutT, bout, out, DIM, DIM);

    // s1: GEMM2 b1
    gemm_f16_mma<float><<<dim3(DIM / BN, M_HALF / BMT), 128, SM128, s1>>>(
        patt + (size_t)M_HALF * DIM, pwoutT, bout,
        out + (size_t)M_HALF * DIM, DIM, DIM);

    // join side stream back into the origin stream
    cudaEventRecord(evD, s1);
    cudaStreamWaitEvent(0, evD, 0);
}

// round 16
// speedup vs baseline: 1.1615x; 1.0384x over previous
#include <cuda_runtime.h>
#include <cuda_fp16.h>
#include <cstdint>
#include <math.h>

#define BB 2
#define SS 2048
#define DIM 1536
#define NH 12
#define HD 128
#define SIGMA 12
#define M_TOT (BB * SS)      // 4096
#define N_QKV (3 * DIM)      // 4608
#define M_HALF (M_TOT / 2)   // 2048 rows per batch

// ---------------- scratch (__device__ globals; allocation-free rule) -------
__device__ __half g_xh[(size_t)M_TOT * DIM];       // permuted x
__device__ __half g_wqkvT[(size_t)N_QKV * DIM];    // permuted Wqkv^T
__device__ __half g_woutT[(size_t)DIM * DIM];      // permuted Wout^T
__device__ __half g_qkvh[(size_t)M_TOT * N_QKV];   // QKV output (fp16, standard)
__device__ __half g_att[(size_t)M_TOT * DIM];      // attention out (permuted)

// ---------------- helpers ---------------------------------------------------
__device__ __forceinline__ uint32_t smem_u32(const void* p) {
    uint32_t a;
    asm("{ .reg .u64 t; cvta.to.shared.u64 t, %1; cvt.u32.u64 %0, t; }"
        : "=r"(a) : "l"(p));
    return a;
}
__device__ __forceinline__ void cp16(uint32_t dst, const void* src) {
    asm volatile("cp.async.cg.shared.global [%0], [%1], 16;"
                 :: "r"(dst), "l"(src) : "memory");
}
__device__ __forceinline__ void cp_commit() {
    asm volatile("cp.async.commit_group;" ::: "memory");
}
template <int N>
__device__ __forceinline__ void cp_wait() {
    asm volatile("cp.async.wait_group %0;" :: "n"(N) : "memory");
}
__device__ __forceinline__ void mma_f16(float* c,
                                        uint32_t a0, uint32_t a1, uint32_t a2, uint32_t a3,
                                        uint32_t b0, uint32_t b1) {
    asm("mma.sync.aligned.m16n8k16.row.col.f32.f16.f16.f32 "
        "{%0,%1,%2,%3}, {%4,%5,%6,%7}, {%8,%9}, {%0,%1,%2,%3};"
        : "+f"(c[0]), "+f"(c[1]), "+f"(c[2]), "+f"(c[3])
        : "r"(a0), "r"(a1), "r"(a2), "r"(a3), "r"(b0), "r"(b1));
}
#define F4U(v, i) (reinterpret_cast<const uint32_t*>(&(v))[i])

// ---------------- fp16 GEMM: CTA 128x128, 4 warps of 64x64, 2 CTAs/SM -------
#define BN 128
#define BMT 128
#define BKH 64               // halves per k-iter (128B rows)
#define STAGES 3

template <typename OutT>
__global__ __launch_bounds__(128, 2)
void gemm_f16_mma(const __half* __restrict__ A, const __half* __restrict__ BT,
                  const float* __restrict__ bias, OutT* __restrict__ C,
                  int Ndim, int K) {
    constexpr int MT = BMT / 32;          // 4 m16 tiles per warp
    constexpr int A_ST = BMT * 128;       // bytes per A stage
    constexpr int B_ST = BN * 128;
    constexpr int STG = A_ST + B_ST;
    extern __shared__ char smem[];
    const uint32_t sbase = smem_u32(smem);

    const int tid = threadIdx.x;
    const int wid = tid >> 5;
    const int lane = tid & 31;
    const int g = lane >> 2;              // 0..7
    const int t = lane & 3;               // 0..3
    const int warp_m = wid >> 1;          // 0..1
    const int warp_n = wid & 1;           // 0..1
    const int m0 = blockIdx.y * BMT;
    const int n0 = blockIdx.x * BN;
    const int KT = K / BKH;

    const int lc = tid & 7;               // loader chunk
    const int lr = tid >> 3;              // loader row base (0..15)

    auto load_stage = [&](int stage, int kt) {
        const __half* Ak = A + (size_t)m0 * K + kt * BKH;
        const __half* Bk = BT + (size_t)n0 * K + kt * BKH;
        const uint32_t sA = sbase + stage * STG;
        const uint32_t sB = sA + A_ST;
#pragma unroll
        for (int i = 0; i < BMT / 16; i++) {
            int row = i * 16 + lr;
            cp16(sA + row * 128 + (((lc + ((row & 1) << 2)) & 7) << 4),
                 Ak + (size_t)row * K + lc * 8);
        }
#pragma unroll
        for (int i = 0; i < BN / 16; i++) {
            int row = i * 16 + lr;
            cp16(sB + row * 128 + (((lc + ((row & 1) << 2)) & 7) << 4),
                 Bk + (size_t)row * K + lc * 8);
        }
        cp_commit();
    };

    float acc[MT][8][4];
#pragma unroll
    for (int i = 0; i < MT; i++)
#pragma unroll
        for (int j = 0; j < 8; j++)
#pragma unroll
            for (int r = 0; r < 4; r++) acc[i][j][r] = 0.0f;

    load_stage(0, 0);
    load_stage(1, 1);

    const int gp = g & 1;                 // row parity for all fragment rows

    for (int kt = 0; kt < KT; ++kt) {
        cp_wait<1>();
        __syncthreads();
        if (kt + 2 < KT) load_stage((kt + 2) % STAGES, kt + 2);

        const char* sA = smem + (kt % STAGES) * STG;
        const char* sB = sA + A_ST;

#pragma unroll
        for (int h = 0; h < 2; h++) {
            const int ch = t + ((h ^ gp) << 2);   // swizzled chunk, 0..7
            float4 av[MT][2];
#pragma unroll
            for (int mt = 0; mt < MT; mt++)
#pragma unroll
                for (int rr = 0; rr < 2; rr++) {
                    int row = warp_m * (BMT / 2) + mt * 16 + rr * 8 + g;
                    av[mt][rr] = *(const float4*)(sA + row * 128 + ch * 16);
                }
            float4 bv[8];
#pragma unroll
            for (int nt = 0; nt < 8; nt++) {
                int row = warp_n * 64 + nt * 8 + g;
                bv[nt] = *(const float4*)(sB + row * 128 + ch * 16);
            }
#pragma unroll
            for (int mt = 0; mt < MT; mt++)
#pragma unroll
                for (int nt = 0; nt < 8; nt++)
                    mma_f16(acc[mt][nt],
                            F4U(av[mt][0], 0), F4U(av[mt][1], 0),
                            F4U(av[mt][0], 1), F4U(av[mt][1], 1),
                            F4U(bv[nt], 0), F4U(bv[nt], 1));
#pragma unroll
            for (int mt = 0; mt < MT; mt++)
#pragma unroll
                for (int nt = 0; nt < 8; nt++)
                    mma_f16(acc[mt][nt],
                            F4U(av[mt][0], 2), F4U(av[mt][1], 2),
                            F4U(av[mt][0], 3), F4U(av[mt][1], 3),
                            F4U(bv[nt], 2), F4U(bv[nt], 3));
        }
    }

    // epilogue: bias in fp32, output fp32 or fp16
#pragma unroll
    for (int mt = 0; mt < MT; mt++) {
        const int r0 = m0 + warp_m * (BMT / 2) + mt * 16 + g;
#pragma unroll
        for (int nt = 0; nt < 8; nt++) {
            const int col = n0 + warp_n * 64 + nt * 8 + 2 * t;
            const float2 bv = *reinterpret_cast<const float2*>(bias + col);
            float2 o0, o1;
            o0.x = acc[mt][nt][0] + bv.x;
            o0.y = acc[mt][nt][1] + bv.y;
            o1.x = acc[mt][nt][2] + bv.x;
            o1.y = acc[mt][nt][3] + bv.y;
            if constexpr (sizeof(OutT) == 4) {
                float* Cf = (float*)C;
                *reinterpret_cast<float2*>(Cf + (size_t)r0 * Ndim + col) = o0;
                *reinterpret_cast<float2*>(Cf + (size_t)(r0 + 8) * Ndim + col) = o1;
            } else {
                __half* Ch = (__half*)C;
                __half2 h0 = __floats2half2_rn(o0.x, o0.y);
                __half2 h1 = __floats2half2_rn(o1.x, o1.y);
                *reinterpret_cast<__half2*>(Ch + (size_t)r0 * Ndim + col) = h0;
                *reinterpret_cast<__half2*>(Ch + (size_t)(r0 + 8) * Ndim + col) = h1;
            }
        }
    }
}

// ---------------- pre-pass kernels ------------------------------------------
__device__ __forceinline__ void transpose_tile(const float* __restrict__ in,
                                               __half* __restrict__ out,
                                               int R, int C, int bx, int by,
                                               int tid) {
    __shared__ float tbuf[32][33];
    const int tx = tid & 31;
    const int ty = tid >> 5;              // 0..7
#pragma unroll
    for (int i = 0; i < 4; i++) {
        int r = by * 32 + ty + i * 8;
        tbuf[ty + i * 8][tx] = in[(size_t)r * C + bx * 32 + tx];
    }
    __syncthreads();
    const int oc = by * 32 + tx;          // K index
    const int w = oc & 31;
    const int ppos = (oc & ~31) | (((w >> 1) & 3) << 3) | ((w >> 3) << 1) | (w & 1);
#pragma unroll
    for (int i = 0; i < 4; i++) {
        int orow = bx * 32 + ty + i * 8;  // N index
        out[(size_t)orow * R + ppos] = __float2half_rn(tbuf[tx][ty + i * 8]);
    }
}

#define NB_X   (M_TOT * DIM / 8 / 256)          // 3072
#define NB_WQ  ((N_QKV / 32) * (DIM / 32))      // 6912
#define NB_WO  ((DIM / 32) * (DIM / 32))        // 2304

// x-perm + WqkvT (needed before GEMM1)
__global__ __launch_bounds__(256)
void prepass_main(const float* __restrict__ x, const float* __restrict__ Wqkv,
                  __half* __restrict__ xh, __half* __restrict__ wqkvT) {
    const int bid = blockIdx.x;
    const int tid = threadIdx.x;
    if (bid < NB_X) {
        int q = bid * 256 + tid;
        int r = q / (DIM / 8);
        int c = q % (DIM / 8);
        int grp = c >> 2, t = c & 3;
        const float* src = x + (size_t)r * DIM + grp * 32 + 2 * t;
        __half2 h0 = __floats2half2_rn(src[0], src[1]);
        __half2 h1 = __floats2half2_rn(src[8], src[9]);
        __half2 h2 = __floats2half2_rn(src[16], src[17]);
        __half2 h3 = __floats2half2_rn(src[24], src[25]);
        uint4 o;
        o.x = *reinterpret_cast<uint32_t*>(&h0);
        o.y = *reinterpret_cast<uint32_t*>(&h1);
        o.z = *reinterpret_cast<uint32_t*>(&h2);
        o.w = *reinterpret_cast<uint32_t*>(&h3);
        reinterpret_cast<uint4*>(xh)[q] = o;
    } else {
        int tile = bid - NB_X;
        int bx = tile % (N_QKV / 32);
        int by = tile / (N_QKV / 32);
        transpose_tile(Wqkv, wqkvT, DIM, N_QKV, bx, by, tid);
    }
}

// WoutT (needed only before GEMM2) — runs on side stream, overlaps GEMM1
__global__ __launch_bounds__(256)
void prepass_wout(const float* __restrict__ Wout, __half* __restrict__ woutT) {
    const int tile = blockIdx.x;
    const int bx = tile % (DIM / 32);
    const int by = tile / (DIM / 32);
    transpose_tile(Wout, woutT, DIM, DIM, bx, by, threadIdx.x);
}

// ---------------- anchor attention (one warp per (h,s) of one batch) --------
__global__ __launch_bounds__(256)
void anchor_attn_kernel(const float* __restrict__ gs, int batch) {
    const int gw = (blockIdx.x * blockDim.x + threadIdx.x) >> 5;
    const int lane = threadIdx.x & 31;

    const int s = gw % SS;
    const int h = gw / SS;                // 0..NH-1
    const int b = batch;

    const float g0 = gs[0], g1 = gs[1], g2 = gs[2];
    const float mx = fmaxf(g0, fmaxf(g1, g2));
    const float lse = mx + logf(expf(g0 - mx) + expf(g1 - mx) + expf(g2 - mx));
    const float lw0 = g0 - lse, lw1 = g1 - lse, lw2 = g2 - lse;

    const __half* base = g_qkvh + (size_t)b * SS * N_QKV;
    const int hc = h * HD + lane * 4;

    float4 q;
    {
        const uint2 qr = *reinterpret_cast<const uint2*>(
            base + (size_t)s * N_QKV + hc);
        float2 a = __half22float2(*reinterpret_cast<const __half2*>(&qr.x));
        float2 c = __half22float2(*reinterpret_cast<const __half2*>(&qr.y));
        q = make_float4(a.x, a.y, c.x, c.y);
    }

    int aidx[SIGMA];
    const int offs[10] = {-3, -2, -1, 1, 2, 3, -10, -5, 5, 10};
#pragma unroll
    for (int a = 0; a < 10; a++) {
        int j = s + offs[a];
        aidx[a] = j < 0 ? 0 : (j > SS - 1 ? SS - 1 : j);
    }
    aidx[10] = 0;
    aidx[11] = SS - 1;

    const float scale = 0.08838834764831845f;
    float sc[SIGMA];
#pragma unroll
    for (int a = 0; a < SIGMA; a++) {
        const uint2 kr = *reinterpret_cast<const uint2*>(
            base + (size_t)aidx[a] * N_QKV + DIM + hc);
        float2 k0 = __half22float2(*reinterpret_cast<const __half2*>(&kr.x));
        float2 k1 = __half22float2(*reinterpret_cast<const __half2*>(&kr.y));
        float d = q.x * k0.x + q.y * k0.y + q.z * k1.x + q.w * k1.y;
#pragma unroll
        for (int o = 16; o > 0; o >>= 1)
            d += __shfl_xor_sync(0xffffffffu, d, o);
        const float lw = (a < 6) ? lw0 : ((a < 10) ? lw1 : lw2);
        sc[a] = d * scale + lw;
    }

    float m = sc[0];
#pragma unroll
    for (int a = 1; a < SIGMA; a++) m = fmaxf(m, sc[a]);
    float sum = 0.0f;
#pragma unroll
    for (int a = 0; a < SIGMA; a++) { sc[a] = __expf(sc[a] - m); sum += sc[a]; }
    const float inv = 1.0f / sum;

    const int cch = lane >> 1;
    const int hs = lane & 1;
    const int d0 = h * HD + (cch >> 2) * 32 + hs * 16 + 2 * (cch & 3);
    float4 acc = make_float4(0.f, 0.f, 0.f, 0.f);
#pragma unroll
    for (int a = 0; a < SIGMA; a++) {
        const float w = sc[a] * inv;
        const __half* vr = base + (size_t)aidx[a] * N_QKV + 2 * DIM + d0;
        float2 v0 = __half22float2(*reinterpret_cast<const __half2*>(vr));
        float2 v1 = __half22float2(*reinterpret_cast<const __half2*>(vr + 8));
        acc.x += w * v0.x; acc.y += w * v0.y;
        acc.z += w * v1.x; acc.w += w * v1.y;
    }

    __half2 p0 = __floats2half2_rn(acc.x, acc.y);
    __half2 p1 = __floats2half2_rn(acc.z, acc.w);
    uint2 o;
    o.x = *reinterpret_cast<uint32_t*>(&p0);
    o.y = *reinterpret_cast<uint32_t*>(&p1);
    *reinterpret_cast<uint2*>(
        g_att + (size_t)(b * SS + s) * DIM + h * HD + cch * 8 + hs * 4) = o;
}

// ---------------------------------------------------------------------------
extern "C" void kernel_launch(void* const* d_in, const int* in_sizes, int n_in,
                              void* d_out, int out_size) {
    const float* x    = (const float*)d_in[0];
    const float* Wqkv = (const float*)d_in[1];
    const float* bqkv = (const float*)d_in[2];
    const float* Wout = (const float*)d_in[3];
    const float* bout = (const float*)d_in[4];
    const float* gsc  = (const float*)d_in[5];
    float* out = (float*)d_out;

    __half *pxh, *pwqkvT, *pwoutT, *patt, *pqkvh;
    cudaGetSymbolAddress((void**)&pxh, g_xh);
    cudaGetSymbolAddress((void**)&pwqkvT, g_wqkvT);
    cudaGetSymbolAddress((void**)&pwoutT, g_woutT);
    cudaGetSymbolAddress((void**)&pqkvh, g_qkvh);
    cudaGetSymbolAddress((void**)&patt, g_att);

    constexpr int SM128 = STAGES * (BMT * 128 + BN * 128);  // 98304

    static cudaStream_t s1;
    static cudaEvent_t ev0, evW, evP, evD;
    static bool init_done = false;
    if (!init_done) {
        cudaFuncSetAttribute((const void*)gemm_f16_mma<__half>,
                             cudaFuncAttributeMaxDynamicSharedMemorySize, SM128);
        cudaFuncSetAttribute((const void*)gemm_f16_mma<float>,
                             cudaFuncAttributeMaxDynamicSharedMemorySize, SM128);
        cudaStreamCreateWithFlags(&s1, cudaStreamNonBlocking);
        cudaEventCreateWithFlags(&ev0, cudaEventDisableTiming);
        cudaEventCreateWithFlags(&evW, cudaEventDisableTiming);
        cudaEventCreateWithFlags(&evP, cudaEventDisableTiming);
        cudaEventCreateWithFlags(&evD, cudaEventDisableTiming);
        init_done = true;
    }

    const int attn_blocks = NH * SS * 32 / 256;   // 3072 per batch

    // fork side stream at entry
    cudaEventRecord(ev0, 0);
    cudaStreamWaitEvent(s1, ev0, 0);

    // s1: WoutT transpose (independent; overlaps prepass_main + GEMM1)
    prepass_wout<<<NB_WO, 256, 0, s1>>>(Wout, pwoutT);
    cudaEventRecord(evW, s1);

    // s0: x-perm + WqkvT
    prepass_main<<<NB_X + NB_WQ, 256>>>(x, Wqkv, pxh, pwqkvT);
    cudaEventRecord(evP, 0);

    // s0: GEMM1 batch 0
    gemm_f16_mma<__half><<<dim3(N_QKV / BN, M_HALF / BMT), 128, SM128>>>(
        pxh, pwqkvT, bqkv, pqkvh, N_QKV, DIM);

    // s1: GEMM1 batch 1 — depends ONLY on prepass_main, queues concurrently
    // with GEMM1 b0 so the scheduler packs both halves into the same waves.
    cudaStreamWaitEvent(s1, evP, 0);
    gemm_f16_mma<__half><<<dim3(N_QKV / BN, M_HALF / BMT), 128, SM128, s1>>>(
        pxh + (size_t)M_HALF * DIM, pwqkvT, bqkv,
        pqkvh + (size_t)M_HALF * N_QKV, N_QKV, DIM);

    // s0: attention b0 (fills idle slots while GEMM1 b1 drains)
    anchor_attn_kernel<<<attn_blocks, 256>>>(gsc, 0);

    // s1: attention b1
    anchor_attn_kernel<<<attn_blocks, 256, 0, s1>>>(gsc, 1);

    // s0: GEMM2 b0 (needs WoutT)
    cudaStreamWaitEvent(0, evW, 0);
    gemm_f16_mma<float><<<dim3(DIM / BN, M_HALF / BMT), 128, SM128>>>(
        patt, pwoutT, bout, out, DIM, DIM);

    // s1: GEMM2 b1 — co-packs with GEMM2 b0
    gemm_f16_mma<float><<<dim3(DIM / BN, M_HALF / BMT), 128, SM128, s1>>>(
        patt + (size_t)M_HALF * DIM, pwoutT, bout,
        out + (size_t)M_HALF * DIM, DIM, DIM);

    // join side stream back into the origin stream
    cudaEventRecord(evD, s1);
    cudaStreamWaitEvent(0, evD, 0);
}

// round 17
// speedup vs baseline: 1.1641x; 1.0023x over previous
#include <cuda_runtime.h>
#include <cuda_fp16.h>
#include <cstdint>
#include <math.h>

#define BB 2
#define SS 2048
#define DIM 1536
#define NH 12
#define HD 128
#define SIGMA 12
#define M_TOT (BB * SS)      // 4096
#define N_QKV (3 * DIM)      // 4608
#define M_HALF (M_TOT / 2)   // 2048 rows per batch

// ---------------- scratch (__device__ globals; allocation-free rule) -------
__device__ __half g_xh[(size_t)M_TOT * DIM];       // permuted x
__device__ __half g_wqkvT[(size_t)N_QKV * DIM];    // permuted Wqkv^T
__device__ __half g_woutT[(size_t)DIM * DIM];      // permuted Wout^T
__device__ __half g_qkvh[(size_t)M_TOT * N_QKV];   // QKV output (fp16, standard)
__device__ __half g_att[(size_t)M_TOT * DIM];      // attention out (permuted)

// ---------------- helpers ---------------------------------------------------
__device__ __forceinline__ uint32_t smem_u32(const void* p) {
    uint32_t a;
    asm("{ .reg .u64 t; cvta.to.shared.u64 t, %1; cvt.u32.u64 %0, t; }"
        : "=r"(a) : "l"(p));
    return a;
}
__device__ __forceinline__ void cp16(uint32_t dst, const void* src) {
    asm volatile("cp.async.cg.shared.global [%0], [%1], 16;"
                 :: "r"(dst), "l"(src) : "memory");
}
__device__ __forceinline__ void cp_commit() {
    asm volatile("cp.async.commit_group;" ::: "memory");
}
template <int N>
__device__ __forceinline__ void cp_wait() {
    asm volatile("cp.async.wait_group %0;" :: "n"(N) : "memory");
}
__device__ __forceinline__ void mma_f16(float* c,
                                        uint32_t a0, uint32_t a1, uint32_t a2, uint32_t a3,
                                        uint32_t b0, uint32_t b1) {
    asm("mma.sync.aligned.m16n8k16.row.col.f32.f16.f16.f32 "
        "{%0,%1,%2,%3}, {%4,%5,%6,%7}, {%8,%9}, {%0,%1,%2,%3};"
        : "+f"(c[0]), "+f"(c[1]), "+f"(c[2]), "+f"(c[3])
        : "r"(a0), "r"(a1), "r"(a2), "r"(a3), "r"(b0), "r"(b1));
}
#define F4U(v, i) (reinterpret_cast<const uint32_t*>(&(v))[i])

// ---------------- fp16 GEMM: CTA 128x128, 4 warps of 64x64, 2 CTAs/SM -------
#define BN 128
#define BMT 128
#define BKH 64               // halves per k-iter (128B rows)
#define STAGES 3

template <typename OutT>
__global__ __launch_bounds__(128, 2)
void gemm_f16_mma(const __half* __restrict__ A, const __half* __restrict__ BT,
                  const float* __restrict__ bias, OutT* __restrict__ C,
                  int Ndim, int K) {
    constexpr int MT = BMT / 32;          // 4 m16 tiles per warp
    constexpr int A_ST = BMT * 128;       // bytes per A stage
    constexpr int B_ST = BN * 128;
    constexpr int STG = A_ST + B_ST;
    extern __shared__ char smem[];
    const uint32_t sbase = smem_u32(smem);

    const int tid = threadIdx.x;
    const int wid = tid >> 5;
    const int lane = tid & 31;
    const int g = lane >> 2;              // 0..7
    const int t = lane & 3;               // 0..3
    const int warp_m = wid >> 1;          // 0..1
    const int warp_n = wid & 1;           // 0..1
    const int m0 = blockIdx.y * BMT;
    const int n0 = blockIdx.x * BN;
    const int KT = K / BKH;

    const int lc = tid & 7;               // loader chunk
    const int lr = tid >> 3;              // loader row base (0..15)

    auto load_stage = [&](int stage, int kt) {
        const __half* Ak = A + (size_t)m0 * K + kt * BKH;
        const __half* Bk = BT + (size_t)n0 * K + kt * BKH;
        const uint32_t sA = sbase + stage * STG;
        const uint32_t sB = sA + A_ST;
#pragma unroll
        for (int i = 0; i < BMT / 16; i++) {
            int row = i * 16 + lr;
            cp16(sA + row * 128 + (((lc + ((row & 1) << 2)) & 7) << 4),
                 Ak + (size_t)row * K + lc * 8);
        }
#pragma unroll
        for (int i = 0; i < BN / 16; i++) {
            int row = i * 16 + lr;
            cp16(sB + row * 128 + (((lc + ((row & 1) << 2)) & 7) << 4),
                 Bk + (size_t)row * K + lc * 8);
        }
        cp_commit();
    };

    float acc[MT][8][4];
#pragma unroll
    for (int i = 0; i < MT; i++)
#pragma unroll
        for (int j = 0; j < 8; j++)
#pragma unroll
            for (int r = 0; r < 4; r++) acc[i][j][r] = 0.0f;

    load_stage(0, 0);
    load_stage(1, 1);

    const int gp = g & 1;                 // row parity for all fragment rows

    for (int kt = 0; kt < KT; ++kt) {
        cp_wait<1>();
        __syncthreads();
        if (kt + 2 < KT) load_stage((kt + 2) % STAGES, kt + 2);

        const char* sA = smem + (kt % STAGES) * STG;
        const char* sB = sA + A_ST;

#pragma unroll
        for (int h = 0; h < 2; h++) {
            const int ch = t + ((h ^ gp) << 2);   // swizzled chunk, 0..7
            float4 av[MT][2];
#pragma unroll
            for (int mt = 0; mt < MT; mt++)
#pragma unroll
                for (int rr = 0; rr < 2; rr++) {
                    int row = warp_m * (BMT / 2) + mt * 16 + rr * 8 + g;
                    av[mt][rr] = *(const float4*)(sA + row * 128 + ch * 16);
                }
            float4 bv[8];
#pragma unroll
            for (int nt = 0; nt < 8; nt++) {
                int row = warp_n * 64 + nt * 8 + g;
                bv[nt] = *(const float4*)(sB + row * 128 + ch * 16);
            }
#pragma unroll
            for (int mt = 0; mt < MT; mt++)
#pragma unroll
                for (int nt = 0; nt < 8; nt++)
                    mma_f16(acc[mt][nt],
                            F4U(av[mt][0], 0), F4U(av[mt][1], 0),
                            F4U(av[mt][0], 1), F4U(av[mt][1], 1),
                            F4U(bv[nt], 0), F4U(bv[nt], 1));
#pragma unroll
            for (int mt = 0; mt < MT; mt++)
#pragma unroll
                for (int nt = 0; nt < 8; nt++)
                    mma_f16(acc[mt][nt],
                            F4U(av[mt][0], 2), F4U(av[mt][1], 2),
                            F4U(av[mt][0], 3), F4U(av[mt][1], 3),
                            F4U(bv[nt], 2), F4U(bv[nt], 3));
        }
    }

    // epilogue: bias in fp32, output fp32 or fp16
#pragma unroll
    for (int mt = 0; mt < MT; mt++) {
        const int r0 = m0 + warp_m * (BMT / 2) + mt * 16 + g;
#pragma unroll
        for (int nt = 0; nt < 8; nt++) {
            const int col = n0 + warp_n * 64 + nt * 8 + 2 * t;
            const float2 bv = *reinterpret_cast<const float2*>(bias + col);
            float2 o0, o1;
            o0.x = acc[mt][nt][0] + bv.x;
            o0.y = acc[mt][nt][1] + bv.y;
            o1.x = acc[mt][nt][2] + bv.x;
            o1.y = acc[mt][nt][3] + bv.y;
            if constexpr (sizeof(OutT) == 4) {
                float* Cf = (float*)C;
                *reinterpret_cast<float2*>(Cf + (size_t)r0 * Ndim + col) = o0;
                *reinterpret_cast<float2*>(Cf + (size_t)(r0 + 8) * Ndim + col) = o1;
            } else {
                __half* Ch = (__half*)C;
                __half2 h0 = __floats2half2_rn(o0.x, o0.y);
                __half2 h1 = __floats2half2_rn(o1.x, o1.y);
                *reinterpret_cast<__half2*>(Ch + (size_t)r0 * Ndim + col) = h0;
                *reinterpret_cast<__half2*>(Ch + (size_t)(r0 + 8) * Ndim + col) = h1;
            }
        }
    }
}

// ---------------- pre-pass kernels ------------------------------------------
__device__ __forceinline__ void transpose_tile(const float* __restrict__ in,
                                               __half* __restrict__ out,
                                               int R, int C, int bx, int by,
                                               int tid) {
    __shared__ float tbuf[32][33];
    const int tx = tid & 31;
    const int ty = tid >> 5;              // 0..7
#pragma unroll
    for (int i = 0; i < 4; i++) {
        int r = by * 32 + ty + i * 8;
        tbuf[ty + i * 8][tx] = in[(size_t)r * C + bx * 32 + tx];
    }
    __syncthreads();
    const int oc = by * 32 + tx;          // K index
    const int w = oc & 31;
    const int ppos = (oc & ~31) | (((w >> 1) & 3) << 3) | ((w >> 3) << 1) | (w & 1);
#pragma unroll
    for (int i = 0; i < 4; i++) {
        int orow = bx * 32 + ty + i * 8;  // N index
        out[(size_t)orow * R + ppos] = __float2half_rn(tbuf[tx][ty + i * 8]);
    }
}

#define NB_X   (M_TOT * DIM / 8 / 256)          // 3072
#define NB_WQ  ((N_QKV / 32) * (DIM / 32))      // 6912
#define NB_WO  ((DIM / 32) * (DIM / 32))        // 2304

// x-perm only (runs on s0, concurrent with WqkvT on s1)
__global__ __launch_bounds__(256)
void prepass_x(const float* __restrict__ x, __half* __restrict__ xh) {
    int q = blockIdx.x * 256 + threadIdx.x;
    int r = q / (DIM / 8);
    int c = q % (DIM / 8);
    int grp = c >> 2, t = c & 3;
    const float* src = x + (size_t)r * DIM + grp * 32 + 2 * t;
    __half2 h0 = __floats2half2_rn(src[0], src[1]);
    __half2 h1 = __floats2half2_rn(src[8], src[9]);
    __half2 h2 = __floats2half2_rn(src[16], src[17]);
    __half2 h3 = __floats2half2_rn(src[24], src[25]);
    uint4 o;
    o.x = *reinterpret_cast<uint32_t*>(&h0);
    o.y = *reinterpret_cast<uint32_t*>(&h1);
    o.z = *reinterpret_cast<uint32_t*>(&h2);
    o.w = *reinterpret_cast<uint32_t*>(&h3);
    reinterpret_cast<uint4*>(xh)[q] = o;
}

// WqkvT transpose (s1, before GEMM1)
__global__ __launch_bounds__(256)
void prepass_wqkv(const float* __restrict__ Wqkv, __half* __restrict__ wqkvT) {
    const int tile = blockIdx.x;
    const int bx = tile % (N_QKV / 32);
    const int by = tile / (N_QKV / 32);
    transpose_tile(Wqkv, wqkvT, DIM, N_QKV, bx, by, threadIdx.x);
}

// WoutT (needed only before GEMM2) — s1, overlaps GEMM1
__global__ __launch_bounds__(256)
void prepass_wout(const float* __restrict__ Wout, __half* __restrict__ woutT) {
    const int tile = blockIdx.x;
    const int bx = tile % (DIM / 32);
    const int by = tile / (DIM / 32);
    transpose_tile(Wout, woutT, DIM, DIM, bx, by, threadIdx.x);
}

// ---------------- anchor attention (one warp per (h,s) of one batch) --------
__global__ __launch_bounds__(256)
void anchor_attn_kernel(const float* __restrict__ gs, int batch) {
    const int gw = (blockIdx.x * blockDim.x + threadIdx.x) >> 5;
    const int lane = threadIdx.x & 31;

    const int s = gw % SS;
    const int h = gw / SS;                // 0..NH-1
    const int b = batch;

    const float g0 = gs[0], g1 = gs[1], g2 = gs[2];
    const float mx = fmaxf(g0, fmaxf(g1, g2));
    const float lse = mx + logf(expf(g0 - mx) + expf(g1 - mx) + expf(g2 - mx));
    const float lw0 = g0 - lse, lw1 = g1 - lse, lw2 = g2 - lse;

    const __half* base = g_qkvh + (size_t)b * SS * N_QKV;
    const int hc = h * HD + lane * 4;

    float4 q;
    {
        const uint2 qr = *reinterpret_cast<const uint2*>(
            base + (size_t)s * N_QKV + hc);
        float2 a = __half22float2(*reinterpret_cast<const __half2*>(&qr.x));
        float2 c = __half22float2(*reinterpret_cast<const __half2*>(&qr.y));
        q = make_float4(a.x, a.y, c.x, c.y);
    }

    int aidx[SIGMA];
    const int offs[10] = {-3, -2, -1, 1, 2, 3, -10, -5, 5, 10};
#pragma unroll
    for (int a = 0; a < 10; a++) {
        int j = s + offs[a];
        aidx[a] = j < 0 ? 0 : (j > SS - 1 ? SS - 1 : j);
    }
    aidx[10] = 0;
    aidx[11] = SS - 1;

    const float scale = 0.08838834764831845f;
    float sc[SIGMA];
#pragma unroll
    for (int a = 0; a < SIGMA; a++) {
        const uint2 kr = *reinterpret_cast<const uint2*>(
            base + (size_t)aidx[a] * N_QKV + DIM + hc);
        float2 k0 = __half22float2(*reinterpret_cast<const __half2*>(&kr.x));
        float2 k1 = __half22float2(*reinterpret_cast<const __half2*>(&kr.y));
        float d = q.x * k0.x + q.y * k0.y + q.z * k1.x + q.w * k1.y;
#pragma unroll
        for (int o = 16; o > 0; o >>= 1)
            d += __shfl_xor_sync(0xffffffffu, d, o);
        const float lw = (a < 6) ? lw0 : ((a < 10) ? lw1 : lw2);
        sc[a] = d * scale + lw;
    }

    float m = sc[0];
#pragma unroll
    for (int a = 1; a < SIGMA; a++) m = fmaxf(m, sc[a]);
    float sum = 0.0f;
#pragma unroll
    for (int a = 0; a < SIGMA; a++) { sc[a] = __expf(sc[a] - m); sum += sc[a]; }
    const float inv = 1.0f / sum;

    const int cch = lane >> 1;
    const int hs = lane & 1;
    const int d0 = h * HD + (cch >> 2) * 32 + hs * 16 + 2 * (cch & 3);
    float4 acc = make_float4(0.f, 0.f, 0.f, 0.f);
#pragma unroll
    for (int a = 0; a < SIGMA; a++) {
        const float w = sc[a] * inv;
        const __half* vr = base + (size_t)aidx[a] * N_QKV + 2 * DIM + d0;
        float2 v0 = __half22float2(*reinterpret_cast<const __half2*>(vr));
        float2 v1 = __half22float2(*reinterpret_cast<const __half2*>(vr + 8));
        acc.x += w * v0.x; acc.y += w * v0.y;
        acc.z += w * v1.x; acc.w += w * v1.y;
    }

    __half2 p0 = __floats2half2_rn(acc.x, acc.y);
    __half2 p1 = __floats2half2_rn(acc.z, acc.w);
    uint2 o;
    o.x = *reinterpret_cast<uint32_t*>(&p0);
    o.y = *reinterpret_cast<uint32_t*>(&p1);
    *reinterpret_cast<uint2*>(
        g_att + (size_t)(b * SS + s) * DIM + h * HD + cch * 8 + hs * 4) = o;
}

// ---------------------------------------------------------------------------
extern "C" void kernel_launch(void* const* d_in, const int* in_sizes, int n_in,
                              void* d_out, int out_size) {
    const float* x    = (const float*)d_in[0];
    const float* Wqkv = (const float*)d_in[1];
    const float* bqkv = (const float*)d_in[2];
    const float* Wout = (const float*)d_in[3];
    const float* bout = (const float*)d_in[4];
    const float* gsc  = (const float*)d_in[5];
    float* out = (float*)d_out;

    __half *pxh, *pwqkvT, *pwoutT, *patt, *pqkvh;
    cudaGetSymbolAddress((void**)&pxh, g_xh);
    cudaGetSymbolAddress((void**)&pwqkvT, g_wqkvT);
    cudaGetSymbolAddress((void**)&pwoutT, g_woutT);
    cudaGetSymbolAddress((void**)&pqkvh, g_qkvh);
    cudaGetSymbolAddress((void**)&patt, g_att);

    constexpr int SM128 = STAGES * (BMT * 128 + BN * 128);  // 98304

    static cudaStream_t s1;
    static cudaEvent_t ev0, evQ, evW, evP, evD;
    static bool init_done = false;
    if (!init_done) {
        cudaFuncSetAttribute((const void*)gemm_f16_mma<__half>,
                             cudaFuncAttributeMaxDynamicSharedMemorySize, SM128);
        cudaFuncSetAttribute((const void*)gemm_f16_mma<float>,
                             cudaFuncAttributeMaxDynamicSharedMemorySize, SM128);
        cudaStreamCreateWithFlags(&s1, cudaStreamNonBlocking);
        cudaEventCreateWithFlags(&ev0, cudaEventDisableTiming);
        cudaEventCreateWithFlags(&evQ, cudaEventDisableTiming);
        cudaEventCreateWithFlags(&evW, cudaEventDisableTiming);
        cudaEventCreateWithFlags(&evP, cudaEventDisableTiming);
        cudaEventCreateWithFlags(&evD, cudaEventDisableTiming);
        init_done = true;
    }

    const int attn_blocks = NH * SS * 32 / 256;   // 3072 per batch

    // fork side stream at entry
    cudaEventRecord(ev0, 0);
    cudaStreamWaitEvent(s1, ev0, 0);

    // s1: WqkvT transpose (concurrent with x-perm on s0), then WoutT
    prepass_wqkv<<<NB_WQ, 256, 0, s1>>>(Wqkv, pwqkvT);
    cudaEventRecord(evQ, s1);
    prepass_wout<<<NB_WO, 256, 0, s1>>>(Wout, pwoutT);
    cudaEventRecord(evW, s1);

    // s0: x-perm (concurrent with WqkvT)
    prepass_x<<<NB_X, 256>>>(x, pxh);
    cudaEventRecord(evP, 0);

    // s0: GEMM1 batch 0 (needs x + WqkvT)
    cudaStreamWaitEvent(0, evQ, 0);
    gemm_f16_mma<__half><<<dim3(N_QKV / BN, M_HALF / BMT), 128, SM128>>>(
        pxh, pwqkvT, bqkv, pqkvh, N_QKV, DIM);

    // s1: GEMM1 batch 1 (needs x; WqkvT by stream order) — co-packs with b0
    cudaStreamWaitEvent(s1, evP, 0);
    gemm_f16_mma<__half><<<dim3(N_QKV / BN, M_HALF / BMT), 128, SM128, s1>>>(
        pxh + (size_t)M_HALF * DIM, pwqkvT, bqkv,
        pqkvh + (size_t)M_HALF * N_QKV, N_QKV, DIM);

    // s0: attention b0 (fills idle slots while GEMM1 b1 drains)
    anchor_attn_kernel<<<attn_blocks, 256>>>(gsc, 0);

    // s1: attention b1
    anchor_attn_kernel<<<attn_blocks, 256, 0, s1>>>(gsc, 1);

    // s0: GEMM2 b0 (needs WoutT)
    cudaStreamWaitEvent(0, evW, 0);
    gemm_f16_mma<float><<<dim3(DIM / BN, M_HALF / BMT), 128, SM128>>>(
        patt, pwoutT, bout, out, DIM, DIM);

    // s1: GEMM2 b1 — co-packs with GEMM2 b0
    gemm_f16_mma<float><<<dim3(DIM / BN, M_HALF / BMT), 128, SM128, s1>>>(
        patt + (size_t)M_HALF * DIM, pwoutT, bout,
        out + (size_t)M_HALF * DIM, DIM, DIM);

    // join side stream back into the origin stream
    cudaEventRecord(evD, s1);
    cudaStreamWaitEvent(0, evD, 0);
}